// round 10
// baseline (speedup 1.0000x reference)
#include <cuda_runtime.h>
#include <cuda_bf16.h>
#include <cstdint>

#define NN   2048      // nodes
#define DD   256       // embedding size
#define CC   768       // cat size
#define VV   2         // variants
#define LL   16        // activities per variant
#define EMAX 32768     // 16*N edges
#define MAXCAND 256

// ---------------- scratch (device globals; no allocation allowed) ----------------
// Encoder iterate chain: e_k = encoder^k(embeddings). Both variants index into it.
__device__ float g_e[LL + 1][NN * DD];              // fp32 chain
__device__ __nv_bfloat16 g_eh[LL + 1][NN * DD];     // bf16 hi plane
__device__ __nv_bfloat16 g_el[LL + 1][NN * DD];     // bf16 lo plane
__device__ __nv_bfloat16 g_msgh[2][NN * DD];        // msg hi per job slot
__device__ __nv_bfloat16 g_msgl[2][NN * DD];        // msg lo per job slot
__device__ float g_pi[VV][NN * CC];
__device__ float g_summary[VV][CC];                 // persistent across steps
__device__ int   g_act[VV][LL];
__device__ int   g_later[VV][LL][LL];
__device__ int   g_laterCnt[VV][LL];
__device__ int   g_has[VV][LL];
__device__ int   g_kidx[VV][LL + 1];                // chain index per variant per step
__device__ int   g_jobs[LL][2];                     // distinct k needing e_{k+1} this step
__device__ int   g_njobs[LL];
__device__ int   g_conflict[LL];                    // jobs[1] == jobs[0]+1 (RAW hazard)
__device__ unsigned g_done;                         // job-0 completion counter (conflict gate)
__device__ int   g_csrCnt[NN];
__device__ int   g_csrOff[NN + 1];
__device__ int   g_csrCur[NN];
__device__ int   g_csrSrc[EMAX];
// W stacked [Wself;Wnbr] transposed: [N=256][K=512], bf16 hi/lo split
__device__ __nv_bfloat16 g_Wt_hi[DD * 2 * DD];
__device__ __nv_bfloat16 g_Wt_lo[DD * 2 * DD];

__device__ __forceinline__ unsigned ld_acq(unsigned* p) {
    unsigned v;
    asm volatile("ld.acquire.gpu.u32 %0, [%1];" : "=r"(v) : "l"(p) : "memory");
    return v;
}

// ---------------- S1: init e_0 (fp32 + hi/lo) / pi / csrCnt + W convert ----------------
__global__ void s1_init_k(const float* __restrict__ embeddings,
                          const float* __restrict__ Wself, const float* __restrict__ Wnbr) {
    int t0 = blockIdx.x * blockDim.x + threadIdx.x;
    int stride = gridDim.x * blockDim.x;
    for (int idx = t0; idx < NN * DD; idx += stride) {
        float e = embeddings[idx];
        g_e[0][idx] = e;
        __nv_bfloat16 hi = __float2bfloat16(e);
        __nv_bfloat16 lo = __float2bfloat16(e - __bfloat162float(hi));
        g_eh[0][idx] = hi;
        g_el[0][idx] = lo;
    }
    for (int idx = t0; idx < VV * NN * CC; idx += stride) {
        ((float*)g_pi)[idx] = 0.0f;
    }
    for (int idx = t0; idx < NN; idx += stride) g_csrCnt[idx] = 0;
    for (int idx = t0; idx < DD * 2 * DD; idx += stride) {
        int n = idx >> 9;           // 0..255
        int k = idx & 511;          // 0..511
        float w = (k < DD) ? Wself[k * DD + n] : Wnbr[(k - DD) * DD + n];
        __nv_bfloat16 hi = __float2bfloat16(w);
        __nv_bfloat16 lo = __float2bfloat16(w - __bfloat162float(hi));
        g_Wt_hi[n * 512 + k] = hi;
        g_Wt_lo[n * 512 + k] = lo;
    }
}

// ---------------- S2: csr_count (blocks 0..127) + prep/schedule (block 128) ----------------
__global__ void s2_prep_count_k(const int* __restrict__ variants, const int* __restrict__ adj,
                                const int* __restrict__ ei, int E) {
    int t = threadIdx.x;                 // 256 threads
    if (blockIdx.x < 128) {
        int t0 = blockIdx.x * 256 + t;
        for (int e = t0; e < E; e += 128 * 256) atomicAdd(&g_csrCnt[ei[E + e]], 1);
        return;
    }
    // prep block
    int warp = t >> 5, lane = t & 31;
    for (int pr = warp; pr < VV * LL; pr += 8) {
        int v = pr >> 4, i = pr & 15;
        int a = variants[v * LL + i];
        if (lane == 0) {
            g_act[v][i] = a;
            int cnt = 0;
            for (int j = i + 1; j < LL; j++) {
                int nd = variants[v * LL + j];
                bool dup = false;
                for (int q = 0; q < cnt; q++) if (g_later[v][i][q] == nd) dup = true;
                if (!dup) g_later[v][i][cnt++] = nd;
            }
            g_laterCnt[v][i] = cnt;
        }
        int any = 0;
        for (int p = lane; p < NN; p += 32) any |= (adj[(size_t)a * NN + p] != 0);
        any = __any_sync(0xffffffffu, any);
        if (lane == 0) g_has[v][i] = any;
    }
    for (int idx = t; idx < VV * CC; idx += 256) {
        ((float*)g_summary)[idx] = 0.0f;
    }
    __syncthreads();
    // schedule: chain indices + per-step job list (single thread; trivial size)
    if (t == 0) {
        for (int v = 0; v < VV; v++) {
            int k = 0;
            g_kidx[v][0] = 0;
            for (int i = 0; i < LL; i++) {
                if (g_has[v][i]) k++;
                g_kidx[v][i + 1] = k;
            }
        }
        for (int i = 0; i < LL; i++) {
            int j0 = -1, j1 = -1, n = 0;
            for (int v = 0; v < VV; v++) {
                if (!g_has[v][i]) continue;
                int k = g_kidx[v][i];
                if (n == 0) { j0 = k; n = 1; }
                else if (k != j0) {
                    if (k < j0) { j1 = j0; j0 = k; } else { j1 = k; }
                    n = 2;
                }
            }
            g_jobs[i][0] = j0;
            g_jobs[i][1] = j1;
            g_njobs[i] = n;
            g_conflict[i] = (n == 2 && j1 == j0 + 1) ? 1 : 0;
        }
    }
}

// ---------------- S3: csr scan + fill (single block) ----------------
__global__ void s3_scan_fill_k(const int* __restrict__ ei, int E) {
    __shared__ int s[2][NN];
    int t = threadIdx.x;                 // 1024 threads
    s[0][t] = g_csrCnt[t];
    s[0][t + 1024] = g_csrCnt[t + 1024];
    __syncthreads();
    int src = 0;
    for (int off = 1; off < NN; off <<= 1) {
        int dstb = src ^ 1;
        for (int idx = t; idx < NN; idx += 1024) {
            int val = s[src][idx];
            if (idx >= off) val += s[src][idx - off];
            s[dstb][idx] = val;
        }
        __syncthreads();
        src = dstb;
    }
    for (int idx = t; idx < NN; idx += 1024) {
        int excl = (idx == 0) ? 0 : s[src][idx - 1];
        g_csrOff[idx] = excl;
        g_csrCur[idx] = excl;
    }
    if (t == 0) g_csrOff[NN] = s[src][NN - 1];
    __syncthreads();
    for (int e = t; e < E; e += 1024) {
        int dst = ei[E + e];
        int pos = atomicAdd(&g_csrCur[dst], 1);
        g_csrSrc[pos] = ei[e];
    }
}

// ---------------- Q: msg gather per job, block = (dst, job), 64 threads ----------------
__global__ __launch_bounds__(64) void q_msg_k(int i) {
    const int p = blockIdx.x, j = blockIdx.y;
    if (p == 0 && j == 0 && threadIdx.x == 0) g_done = 0;   // reset conflict gate for R(i)
    if (j >= g_njobs[i]) return;
    const int k = g_jobs[i][j];

    __shared__ int sidx[64];
    const float4* __restrict__ emb4 = (const float4*)g_e[k];
    const int t = threadIdx.x;           // 64 threads x float4 = 256 cols
    float4 acc = make_float4(0.f, 0.f, 0.f, 0.f);
    const int s0 = g_csrOff[p];
    const int deg = g_csrOff[p + 1] - s0;

    for (int base = 0; base < deg; base += 64) {
        int chunk = min(64, deg - base);
        if (base) __syncthreads();
        if (t < chunk) sidx[t] = g_csrSrc[s0 + base + t];
        __syncthreads();
#pragma unroll 8
        for (int jj = 0; jj < chunk; jj++) {
            float4 e = __ldg(&emb4[(size_t)sidx[jj] * (DD / 4) + t]);
            acc.x += e.x; acc.y += e.y; acc.z += e.z; acc.w += e.w;
        }
    }
    __nv_bfloat162 h0 = __floats2bfloat162_rn(acc.x, acc.y);
    __nv_bfloat162 h1 = __floats2bfloat162_rn(acc.z, acc.w);
    __nv_bfloat162 l0 = __floats2bfloat162_rn(acc.x - __bfloat162float(h0.x),
                                              acc.y - __bfloat162float(h0.y));
    __nv_bfloat162 l1 = __floats2bfloat162_rn(acc.z - __bfloat162float(h1.x),
                                              acc.w - __bfloat162float(h1.y));
    size_t off = (size_t)p * DD + t * 4;
    *(__nv_bfloat162*)&g_msgh[j][off]     = h0;
    *(__nv_bfloat162*)&g_msgh[j][off + 2] = h1;
    *(__nv_bfloat162*)&g_msgl[j][off]     = l0;
    *(__nv_bfloat162*)&g_msgl[j][off + 2] = l1;
}

// ---------------- GEMM helpers ----------------
#define SA 40
#define SB 40

__device__ __forceinline__ void mma16816(float* c, const uint32_t* a, const uint32_t* b) {
    asm volatile(
        "mma.sync.aligned.m16n8k16.row.col.f32.bf16.bf16.f32 "
        "{%0,%1,%2,%3}, {%4,%5,%6,%7}, {%8,%9}, {%0,%1,%2,%3};"
        : "+f"(c[0]), "+f"(c[1]), "+f"(c[2]), "+f"(c[3])
        : "r"(a[0]), "r"(a[1]), "r"(a[2]), "r"(a[3]), "r"(b[0]), "r"(b[1]));
}
__device__ __forceinline__ void ldsm4(uint32_t* r, uint32_t addr) {
    asm volatile("ldmatrix.sync.aligned.m8n8.x4.shared.b16 {%0,%1,%2,%3}, [%4];"
        : "=r"(r[0]), "=r"(r[1]), "=r"(r[2]), "=r"(r[3]) : "r"(addr));
}

// ---------------- R: GEMM jobs (blocks 0..127) + stepA/BC (block 128), 256 threads ----------------
// blocks 0..63 -> job 0 (64 tiles of M=2048), 64..127 -> job 1, 128 -> stepABC
__global__ __launch_bounds__(256) void r_k(const int* __restrict__ adj,
                                           const float* __restrict__ bias, int i) {
    const int bx = blockIdx.x;
    const int t = threadIdx.x;
    const int lane = t & 31;
    const int warp = t >> 5;

    __shared__ __align__(16) __nv_bfloat16 As[2][128][SA];   // [hi/lo]
    __shared__ __align__(16) __nv_bfloat16 Bs[2][64][SB];
    __shared__ float s_delta[VV][CC];
    __shared__ int s_cand[VV][MAXCAND];
    __shared__ unsigned s_dmask[VV][MAXCAND];
    __shared__ int s_ncand[VV];

    if (bx == 128) {
        // ============ stepA + stepBC, whole step, one block ============
        for (int idx = t; idx < VV * CC; idx += 256) ((float*)s_delta)[idx] = 0.f;
        if (t < VV) s_ncand[t] = 0;
        __syncthreads();

        // Phase A: candidate scan (followers of a) — adj only
        for (int v = 0; v < VV; v++) {
            if (!g_has[v][i]) continue;
            const int a = g_act[v][i];
            for (int p = t; p < NN; p += 256) {
                if (adj[(size_t)a * NN + p] != 0) {
                    int id = atomicAdd(&s_ncand[v], 1);
                    if (id < MAXCAND) s_cand[v][id] = p;
                }
            }
        }
        __syncthreads();

        // Phase B: dest-set probe, warp per candidate — adj only
        for (int v = 0; v < VV; v++) {
            if (!g_has[v][i]) continue;
            int nc = min(s_ncand[v], MAXCAND);
            const int cnt = g_laterCnt[v][i];
            for (int c = warp; c < nc; c += 8) {
                int p = s_cand[v][c];
                int hit = (lane < cnt) ? (adj[(size_t)p * NN + g_later[v][i][lane]] != 0) : 0;
                unsigned dm = __ballot_sync(0xffffffffu, hit);
                if (lane == 0) s_dmask[v][c] = dm;
            }
        }
        __syncthreads();

        // Conflict gate: if job 0 writes e_{k} that one variant reads below, wait it out.
        if (g_conflict[i]) {
            if (t == 0) { while (ld_acq(&g_done) < 64) {} }
            __syncthreads();
        }

        // Phase C: pi[p] += cat; delta += pi_new  (warp per masked candidate)
        for (int v = 0; v < VV; v++) {
            if (!g_has[v][i]) continue;
            int nc = min(s_ncand[v], MAXCAND);
            const int a = g_act[v][i];
            const float* emb = g_e[g_kidx[v][i]];
            for (int c = warp; c < nc; c += 8) {
                unsigned dm = s_dmask[v][c];
                if (!dm) continue;
                int p = s_cand[v][c];
#pragma unroll
                for (int ch = 0; ch < 6; ch++) {
                    int col = ch * 128 + lane * 4;       // 0..764
                    float4 cat;
                    if (col < 256) {
                        cat = *(const float4*)&emb[(size_t)p * DD + col];
                    } else if (col < 512) {
                        cat = *(const float4*)&emb[(size_t)a * DD + (col - 256)];
                    } else {
                        cat = make_float4(0.f, 0.f, 0.f, 0.f);
                        unsigned m = dm;
                        while (m) {
                            int q = __ffs(m) - 1; m &= m - 1;
                            int lk = g_later[v][i][q];
                            float4 e = *(const float4*)&emb[(size_t)lk * DD + (col - 512)];
                            cat.x += e.x; cat.y += e.y; cat.z += e.z; cat.w += e.w;
                        }
                    }
                    float* pir = &g_pi[v][(size_t)p * CC + col];
                    float4 pn = *(float4*)pir;
                    pn.x += cat.x; pn.y += cat.y; pn.z += cat.z; pn.w += cat.w;
                    *(float4*)pir = pn;
                    atomicAdd(&s_delta[v][col + 0], pn.x);
                    atomicAdd(&s_delta[v][col + 1], pn.y);
                    atomicAdd(&s_delta[v][col + 2], pn.z);
                    atomicAdd(&s_delta[v][col + 3], pn.w);
                }
            }
        }
        __syncthreads();

        // Phase D: summary_new = summary_old + delta; persist
        for (int v = 0; v < VV; v++) {
            if (!g_has[v][i]) continue;
            if (t < 192) {
                float4 s = *(float4*)&g_summary[v][t * 4];
                float4 d = *(float4*)&s_delta[v][t * 4];
                s.x += d.x; s.y += d.y; s.z += d.z; s.w += d.w;
                *(float4*)&g_summary[v][t * 4] = s;
                *(float4*)&s_delta[v][t * 4] = s;
            }
        }
        __syncthreads();

        // Phase E: pi[masked] += summary_new
        for (int v = 0; v < VV; v++) {
            if (!g_has[v][i]) continue;
            int nc = min(s_ncand[v], MAXCAND);
            for (int c = warp; c < nc; c += 8) {
                if (!s_dmask[v][c]) continue;
                int p = s_cand[v][c];
#pragma unroll
                for (int ch = 0; ch < 6; ch++) {
                    int col = ch * 128 + lane * 4;
                    float4 s = *(float4*)&s_delta[v][col];
                    float* pir = &g_pi[v][(size_t)p * CC + col];
                    float4 o = *(float4*)pir;
                    o.x += s.x; o.y += s.y; o.z += s.z; o.w += s.w;
                    *(float4*)pir = o;
                }
            }
        }
        return;
    }

    // ============ GEMM: job = bx>>6, tile = bx&63 ============
    const int j = bx >> 6;
    if (j >= g_njobs[i]) return;
    const int k = g_jobs[i][j];
    const int conflict = g_conflict[i];
    if (j == 1 && conflict) {
        // job 1 reads e_{k} = e_{jobs[0]+1}, being written by job 0: wait.
        if (t == 0) { while (ld_acq(&g_done) < 64) {} }
        __syncthreads();
    }
    const int tile = bx & 63;
    const int m0 = (tile >> 2) * 128;    // M = 2048
    const int n0 = (tile & 3) * 64;

    const int wm = warp >> 1;            // 0..3
    const int wn = warp & 1;             // 0..1
    const int g8 = lane >> 2;
    const int tq = lane & 3;

    float acc[2][4][4];
#pragma unroll
    for (int mt = 0; mt < 2; mt++)
#pragma unroll
        for (int nt = 0; nt < 4; nt++)
#pragma unroll
            for (int e = 0; e < 4; e++) acc[mt][nt][e] = 0.f;

    // precompute ldmatrix lane addresses
    uint32_t aaddr[2][2], baddr[2][2];   // [mt|q][h]
    {
        int arow = wm * 32 + (lane & 15);
        int acol = (lane >> 4) * 8;
        aaddr[0][0] = (uint32_t)__cvta_generic_to_shared(&As[0][arow][acol]);
        aaddr[1][0] = (uint32_t)__cvta_generic_to_shared(&As[0][arow + 16][acol]);
        aaddr[0][1] = (uint32_t)__cvta_generic_to_shared(&As[1][arow][acol]);
        aaddr[1][1] = (uint32_t)__cvta_generic_to_shared(&As[1][arow + 16][acol]);
        int brow = wn * 32 + (lane & 7) + ((lane >> 4) << 3);
        int bcol = ((lane >> 3) & 1) * 8;
        baddr[0][0] = (uint32_t)__cvta_generic_to_shared(&Bs[0][brow][bcol]);
        baddr[1][0] = (uint32_t)__cvta_generic_to_shared(&Bs[0][brow + 16][bcol]);
        baddr[0][1] = (uint32_t)__cvta_generic_to_shared(&Bs[1][brow][bcol]);
        baddr[1][1] = (uint32_t)__cvta_generic_to_shared(&Bs[1][brow + 16][bcol]);
    }

    // A loader: thread -> (aq = 8-col group 0..3, ar = row 0..63; rows ar, ar+64)
    const int aq = t & 3;
    const int ar = t >> 2;
    const int bn = t >> 2;
    const int bseg = t & 3;

    const __nv_bfloat16* __restrict__ Xh = g_eh[k];
    const __nv_bfloat16* __restrict__ Xl = g_el[k];
    const __nv_bfloat16* __restrict__ Mh = g_msgh[j];
    const __nv_bfloat16* __restrict__ Ml = g_msgl[j];

    for (int kt = 0; kt < 512; kt += 32) {
        const __nv_bfloat16* Ah = (kt < 256) ? Xh : Mh;
        const __nv_bfloat16* Al = (kt < 256) ? Xl : Ml;
        int colbase = (kt & 255) + aq * 8;
        size_t o0 = (size_t)(m0 + ar) * DD + colbase;
        size_t o1 = (size_t)(m0 + ar + 64) * DD + colbase;
        uint4 h0 = *(const uint4*)&Ah[o0];
        uint4 h1 = *(const uint4*)&Ah[o1];
        uint4 l0 = *(const uint4*)&Al[o0];
        uint4 l1 = *(const uint4*)&Al[o1];
        *(uint4*)&As[0][ar][aq * 8]      = h0;
        *(uint4*)&As[0][ar + 64][aq * 8] = h1;
        *(uint4*)&As[1][ar][aq * 8]      = l0;
        *(uint4*)&As[1][ar + 64][aq * 8] = l1;
        {
            size_t woff = (size_t)(n0 + bn) * 512 + kt + bseg * 8;
            *(uint4*)&Bs[0][bn][bseg * 8] = *(const uint4*)&g_Wt_hi[woff];
            *(uint4*)&Bs[1][bn][bseg * 8] = *(const uint4*)&g_Wt_lo[woff];
        }
        __syncthreads();

#pragma unroll
        for (int sub = 0; sub < 2; sub++) {
            uint32_t off = sub * 32;     // 16 bf16 = 32 bytes
            uint32_t ah0[4], ah1[4], al0[4], al1[4];
            uint32_t bh0[4], bh1[4], bl0[4], bl1[4];
            ldsm4(ah0, aaddr[0][0] + off);
            ldsm4(ah1, aaddr[1][0] + off);
            ldsm4(al0, aaddr[0][1] + off);
            ldsm4(al1, aaddr[1][1] + off);
            ldsm4(bh0, baddr[0][0] + off);
            ldsm4(bh1, baddr[1][0] + off);
            ldsm4(bl0, baddr[0][1] + off);
            ldsm4(bl1, baddr[1][1] + off);
#pragma unroll
            for (int mt = 0; mt < 2; mt++) {
                const uint32_t* ah = mt ? ah1 : ah0;
                const uint32_t* al = mt ? al1 : al0;
                mma16816(acc[mt][0], ah, bh0 + 0);
                mma16816(acc[mt][0], ah, bl0 + 0);
                mma16816(acc[mt][0], al, bh0 + 0);
                mma16816(acc[mt][1], ah, bh0 + 2);
                mma16816(acc[mt][1], ah, bl0 + 2);
                mma16816(acc[mt][1], al, bh0 + 2);
                mma16816(acc[mt][2], ah, bh1 + 0);
                mma16816(acc[mt][2], ah, bl1 + 0);
                mma16816(acc[mt][2], al, bh1 + 0);
                mma16816(acc[mt][3], ah, bh1 + 2);
                mma16816(acc[mt][3], ah, bl1 + 2);
                mma16816(acc[mt][3], al, bh1 + 2);
            }
        }
        __syncthreads();
    }

    // epilogue: + bias, relu, store fp32 + bf16 hi/lo planes into e_{k+1}
    float* O = g_e[k + 1];
    __nv_bfloat16* Oh = g_eh[k + 1];
    __nv_bfloat16* Ol = g_el[k + 1];
#pragma unroll
    for (int mt = 0; mt < 2; mt++) {
        int row = m0 + wm * 32 + mt * 16 + g8;
#pragma unroll
        for (int nt = 0; nt < 4; nt++) {
            int col = n0 + wn * 32 + nt * 8 + tq * 2;
            float b0 = bias[col], b1 = bias[col + 1];
            float2 o0, o1;
            o0.x = fmaxf(acc[mt][nt][0] + b0, 0.f);
            o0.y = fmaxf(acc[mt][nt][1] + b1, 0.f);
            o1.x = fmaxf(acc[mt][nt][2] + b0, 0.f);
            o1.y = fmaxf(acc[mt][nt][3] + b1, 0.f);
            *(float2*)&O[(size_t)row * DD + col] = o0;
            *(float2*)&O[(size_t)(row + 8) * DD + col] = o1;
            __nv_bfloat162 h0 = __floats2bfloat162_rn(o0.x, o0.y);
            __nv_bfloat162 l0 = __floats2bfloat162_rn(o0.x - __bfloat162float(h0.x),
                                                      o0.y - __bfloat162float(h0.y));
            __nv_bfloat162 h1 = __floats2bfloat162_rn(o1.x, o1.y);
            __nv_bfloat162 l1 = __floats2bfloat162_rn(o1.x - __bfloat162float(h1.x),
                                                      o1.y - __bfloat162float(h1.y));
            *(__nv_bfloat162*)&Oh[(size_t)row * DD + col]       = h0;
            *(__nv_bfloat162*)&Ol[(size_t)row * DD + col]       = l0;
            *(__nv_bfloat162*)&Oh[(size_t)(row + 8) * DD + col] = h1;
            *(__nv_bfloat162*)&Ol[(size_t)(row + 8) * DD + col] = l1;
        }
    }
    // conflict gate arrival (job 0 only)
    if (conflict && j == 0) {
        __syncthreads();
        __threadfence();
        if (t == 0) atomicAdd(&g_done, 1u);
    }
}

// ---------------- final: out = pi[0] + pi[1] ----------------
__global__ void sum_out_k(float* __restrict__ out) {
    int t0 = blockIdx.x * blockDim.x + threadIdx.x;
    int stride = gridDim.x * blockDim.x;
    const float4* p0 = (const float4*)g_pi[0];
    const float4* p1 = (const float4*)g_pi[1];
    float4* o4 = (float4*)out;
    int total = NN * CC / 4;
    for (int idx = t0; idx < total; idx += stride) {
        float4 a = p0[idx], b = p1[idx];
        o4[idx] = make_float4(a.x + b.x, a.y + b.y, a.z + b.z, a.w + b.w);
    }
}

// ---------------- launch ----------------
extern "C" void kernel_launch(void* const* d_in, const int* in_sizes, int n_in,
                              void* d_out, int out_size) {
    const float* embeddings = (const float*)d_in[0];
    const float* Wself      = (const float*)d_in[1];
    const float* Wnbr       = (const float*)d_in[2];
    const float* bvec       = (const float*)d_in[3];
    const int*   variants   = (const int*)d_in[4];
    const int*   original   = (const int*)d_in[5];
    const int*   edge_index = (const int*)d_in[6];
    float* out = (float*)d_out;
    int E = in_sizes[6] / 2;

    s1_init_k<<<512, 256>>>(embeddings, Wself, Wnbr);
    s2_prep_count_k<<<129, 256>>>(variants, original, edge_index, E);
    s3_scan_fill_k<<<1, 1024>>>(edge_index, E);

    for (int i = 0; i < LL; i++) {
        q_msg_k<<<dim3(NN, 2), 64>>>(i);
        r_k<<<129, 256>>>(original, bvec, i);
    }

    sum_out_k<<<1024, 256>>>(out);
}

// round 11
// speedup vs baseline: 1.0468x; 1.0468x over previous
#include <cuda_runtime.h>
#include <cuda_bf16.h>
#include <cstdint>

#define NN   2048      // nodes
#define DD   256       // embedding size
#define CC   768       // cat size
#define VV   2         // variants
#define LL   16        // activities per variant
#define EMAX 32768     // 16*N edges
#define MAXCAND 256

// ---------------- scratch (device globals; no allocation allowed) ----------------
// Encoder iterate chain: e_k = encoder^k(embeddings). Both variants index into it.
__device__ float g_e[LL + 1][NN * DD];              // fp32 chain
__device__ __nv_bfloat16 g_eh[LL + 1][NN * DD];     // bf16 hi plane
__device__ __nv_bfloat16 g_el[LL + 1][NN * DD];     // bf16 lo plane
__device__ __nv_bfloat16 g_msgh[2][NN * DD];        // msg hi per job slot
__device__ __nv_bfloat16 g_msgl[2][NN * DD];        // msg lo per job slot
__device__ float g_pi[VV][NN * CC];
__device__ float g_summary[VV][CC];                 // persistent across steps
__device__ int   g_act[VV][LL];
__device__ int   g_later[VV][LL][LL];
__device__ int   g_laterCnt[VV][LL];
__device__ int   g_has[VV][LL];
__device__ int   g_kidx[VV][LL + 1];                // chain index per variant per step
__device__ int   g_jobs[LL][2];                     // distinct k needing e_{k+1} this step
__device__ int   g_njobs[LL];
__device__ int   g_conflict[LL];                    // jobs[1] == jobs[0]+1 (RAW hazard)
__device__ unsigned g_done;                         // job-0 completion counter (conflict gate)
__device__ int   g_csrCnt[NN];
__device__ int   g_csrOff[NN + 1];
__device__ int   g_csrCur[NN];
__device__ int   g_csrSrc[EMAX];
// W stacked [Wself;Wnbr] transposed: [N=256][K=512], bf16 hi/lo split
__device__ __nv_bfloat16 g_Wt_hi[DD * 2 * DD];
__device__ __nv_bfloat16 g_Wt_lo[DD * 2 * DD];

__device__ __forceinline__ unsigned ld_acq(unsigned* p) {
    unsigned v;
    asm volatile("ld.acquire.gpu.u32 %0, [%1];" : "=r"(v) : "l"(p) : "memory");
    return v;
}

// ---------------- S1: init e_0 (fp32 + hi/lo) / pi / csrCnt + W convert ----------------
__global__ void s1_init_k(const float* __restrict__ embeddings,
                          const float* __restrict__ Wself, const float* __restrict__ Wnbr) {
    int t0 = blockIdx.x * blockDim.x + threadIdx.x;
    int stride = gridDim.x * blockDim.x;
    for (int idx = t0; idx < NN * DD; idx += stride) {
        float e = embeddings[idx];
        g_e[0][idx] = e;
        __nv_bfloat16 hi = __float2bfloat16(e);
        __nv_bfloat16 lo = __float2bfloat16(e - __bfloat162float(hi));
        g_eh[0][idx] = hi;
        g_el[0][idx] = lo;
    }
    for (int idx = t0; idx < VV * NN * CC; idx += stride) {
        ((float*)g_pi)[idx] = 0.0f;
    }
    for (int idx = t0; idx < NN; idx += stride) g_csrCnt[idx] = 0;
    for (int idx = t0; idx < DD * 2 * DD; idx += stride) {
        int n = idx >> 9;           // 0..255
        int k = idx & 511;          // 0..511
        float w = (k < DD) ? Wself[k * DD + n] : Wnbr[(k - DD) * DD + n];
        __nv_bfloat16 hi = __float2bfloat16(w);
        __nv_bfloat16 lo = __float2bfloat16(w - __bfloat162float(hi));
        g_Wt_hi[n * 512 + k] = hi;
        g_Wt_lo[n * 512 + k] = lo;
    }
}

// ---------------- S2: csr_count (blocks 0..127) + prep/schedule (block 128) ----------------
__global__ void s2_prep_count_k(const int* __restrict__ variants, const int* __restrict__ adj,
                                const int* __restrict__ ei, int E) {
    int t = threadIdx.x;                 // 256 threads
    if (blockIdx.x < 128) {
        int t0 = blockIdx.x * 256 + t;
        for (int e = t0; e < E; e += 128 * 256) atomicAdd(&g_csrCnt[ei[E + e]], 1);
        return;
    }
    // prep block
    int warp = t >> 5, lane = t & 31;
    for (int pr = warp; pr < VV * LL; pr += 8) {
        int v = pr >> 4, i = pr & 15;
        int a = variants[v * LL + i];
        if (lane == 0) {
            g_act[v][i] = a;
            int cnt = 0;
            for (int j = i + 1; j < LL; j++) {
                int nd = variants[v * LL + j];
                bool dup = false;
                for (int q = 0; q < cnt; q++) if (g_later[v][i][q] == nd) dup = true;
                if (!dup) g_later[v][i][cnt++] = nd;
            }
            g_laterCnt[v][i] = cnt;
        }
        int any = 0;
        for (int p = lane; p < NN; p += 32) any |= (adj[(size_t)a * NN + p] != 0);
        any = __any_sync(0xffffffffu, any);
        if (lane == 0) g_has[v][i] = any;
    }
    for (int idx = t; idx < VV * CC; idx += 256) {
        ((float*)g_summary)[idx] = 0.0f;
    }
    __syncthreads();
    // schedule: chain indices + per-step job list (single thread; trivial size)
    if (t == 0) {
        for (int v = 0; v < VV; v++) {
            int k = 0;
            g_kidx[v][0] = 0;
            for (int i = 0; i < LL; i++) {
                if (g_has[v][i]) k++;
                g_kidx[v][i + 1] = k;
            }
        }
        for (int i = 0; i < LL; i++) {
            int j0 = -1, j1 = -1, n = 0;
            for (int v = 0; v < VV; v++) {
                if (!g_has[v][i]) continue;
                int k = g_kidx[v][i];
                if (n == 0) { j0 = k; n = 1; }
                else if (k != j0) {
                    if (k < j0) { j1 = j0; j0 = k; } else { j1 = k; }
                    n = 2;
                }
            }
            g_jobs[i][0] = j0;
            g_jobs[i][1] = j1;
            g_njobs[i] = n;
            g_conflict[i] = (n == 2 && j1 == j0 + 1) ? 1 : 0;
        }
    }
}

// ---------------- S3: csr scan + fill (single block) ----------------
__global__ void s3_scan_fill_k(const int* __restrict__ ei, int E) {
    __shared__ int s[2][NN];
    int t = threadIdx.x;                 // 1024 threads
    s[0][t] = g_csrCnt[t];
    s[0][t + 1024] = g_csrCnt[t + 1024];
    __syncthreads();
    int src = 0;
    for (int off = 1; off < NN; off <<= 1) {
        int dstb = src ^ 1;
        for (int idx = t; idx < NN; idx += 1024) {
            int val = s[src][idx];
            if (idx >= off) val += s[src][idx - off];
            s[dstb][idx] = val;
        }
        __syncthreads();
        src = dstb;
    }
    for (int idx = t; idx < NN; idx += 1024) {
        int excl = (idx == 0) ? 0 : s[src][idx - 1];
        g_csrOff[idx] = excl;
        g_csrCur[idx] = excl;
    }
    if (t == 0) g_csrOff[NN] = s[src][NN - 1];
    __syncthreads();
    for (int e = t; e < E; e += 1024) {
        int dst = ei[E + e];
        int pos = atomicAdd(&g_csrCur[dst], 1);
        g_csrSrc[pos] = ei[e];
    }
}

// ---------------- Q: msg gather per job, block = (dst, job), 64 threads ----------------
__global__ __launch_bounds__(64) void q_msg_k(int i) {
    const int p = blockIdx.x, j = blockIdx.y;
    if (p == 0 && j == 0 && threadIdx.x == 0) g_done = 0;   // reset conflict gate for R(i)
    if (j >= g_njobs[i]) return;
    const int k = g_jobs[i][j];

    __shared__ int sidx[64];
    const float4* __restrict__ emb4 = (const float4*)g_e[k];
    const int t = threadIdx.x;           // 64 threads x float4 = 256 cols
    float4 acc = make_float4(0.f, 0.f, 0.f, 0.f);
    const int s0 = g_csrOff[p];
    const int deg = g_csrOff[p + 1] - s0;

    for (int base = 0; base < deg; base += 64) {
        int chunk = min(64, deg - base);
        if (base) __syncthreads();
        if (t < chunk) sidx[t] = g_csrSrc[s0 + base + t];
        __syncthreads();
#pragma unroll 8
        for (int jj = 0; jj < chunk; jj++) {
            float4 e = __ldg(&emb4[(size_t)sidx[jj] * (DD / 4) + t]);
            acc.x += e.x; acc.y += e.y; acc.z += e.z; acc.w += e.w;
        }
    }
    __nv_bfloat162 h0 = __floats2bfloat162_rn(acc.x, acc.y);
    __nv_bfloat162 h1 = __floats2bfloat162_rn(acc.z, acc.w);
    __nv_bfloat162 l0 = __floats2bfloat162_rn(acc.x - __bfloat162float(h0.x),
                                              acc.y - __bfloat162float(h0.y));
    __nv_bfloat162 l1 = __floats2bfloat162_rn(acc.z - __bfloat162float(h1.x),
                                              acc.w - __bfloat162float(h1.y));
    size_t off = (size_t)p * DD + t * 4;
    *(__nv_bfloat162*)&g_msgh[j][off]     = h0;
    *(__nv_bfloat162*)&g_msgh[j][off + 2] = h1;
    *(__nv_bfloat162*)&g_msgl[j][off]     = l0;
    *(__nv_bfloat162*)&g_msgl[j][off + 2] = l1;
}

// ---------------- GEMM helpers ----------------
#define SA 40
#define SB 40

__device__ __forceinline__ void mma16816(float* c, const uint32_t* a, const uint32_t* b) {
    asm volatile(
        "mma.sync.aligned.m16n8k16.row.col.f32.bf16.bf16.f32 "
        "{%0,%1,%2,%3}, {%4,%5,%6,%7}, {%8,%9}, {%0,%1,%2,%3};"
        : "+f"(c[0]), "+f"(c[1]), "+f"(c[2]), "+f"(c[3])
        : "r"(a[0]), "r"(a[1]), "r"(a[2]), "r"(a[3]), "r"(b[0]), "r"(b[1]));
}
__device__ __forceinline__ void ldsm4(uint32_t* r, uint32_t addr) {
    asm volatile("ldmatrix.sync.aligned.m8n8.x4.shared.b16 {%0,%1,%2,%3}, [%4];"
        : "=r"(r[0]), "=r"(r[1]), "=r"(r[2]), "=r"(r[3]) : "r"(addr));
}

// ---------------- R: GEMM jobs (blocks 0..127) + stepA/BC (block 128), 256 threads ----------------
// blocks 0..63 -> job 0 (64 tiles of M=2048), 64..127 -> job 1, 128 -> stepABC
__global__ __launch_bounds__(256) void r_k(const int* __restrict__ adj,
                                           const float* __restrict__ bias, int i) {
    const int bx = blockIdx.x;
    const int t = threadIdx.x;
    const int lane = t & 31;
    const int warp = t >> 5;

    __shared__ __align__(16) __nv_bfloat16 As[2][128][SA];   // [hi/lo]
    __shared__ __align__(16) __nv_bfloat16 Bs[2][64][SB];
    __shared__ float s_delta[VV][CC];
    __shared__ int s_cand[VV][MAXCAND];
    __shared__ unsigned s_dmask[VV][MAXCAND];
    __shared__ int s_ncand[VV];

    if (bx == 128) {
        // ============ stepA + stepBC, whole step, one block ============
        for (int idx = t; idx < VV * CC; idx += 256) ((float*)s_delta)[idx] = 0.f;
        if (t < VV) s_ncand[t] = 0;
        __syncthreads();

        // Phase A: candidate scan (followers of a) — adj only
        for (int v = 0; v < VV; v++) {
            if (!g_has[v][i]) continue;
            const int a = g_act[v][i];
            for (int p = t; p < NN; p += 256) {
                if (adj[(size_t)a * NN + p] != 0) {
                    int id = atomicAdd(&s_ncand[v], 1);
                    if (id < MAXCAND) s_cand[v][id] = p;
                }
            }
        }
        __syncthreads();

        // Phase B: dest-set probe, warp per candidate — adj only
        for (int v = 0; v < VV; v++) {
            if (!g_has[v][i]) continue;
            int nc = min(s_ncand[v], MAXCAND);
            const int cnt = g_laterCnt[v][i];
            for (int c = warp; c < nc; c += 8) {
                int p = s_cand[v][c];
                int hit = (lane < cnt) ? (adj[(size_t)p * NN + g_later[v][i][lane]] != 0) : 0;
                unsigned dm = __ballot_sync(0xffffffffu, hit);
                if (lane == 0) s_dmask[v][c] = dm;
            }
        }
        __syncthreads();

        // Conflict gate: if job 0 writes e_{k} that one variant reads below, wait it out.
        if (g_conflict[i]) {
            if (t == 0) { while (ld_acq(&g_done) < 64) {} }
            __syncthreads();
        }

        // Phase C: pi[p] += cat; delta += pi_new  (warp per masked candidate)
        for (int v = 0; v < VV; v++) {
            if (!g_has[v][i]) continue;
            int nc = min(s_ncand[v], MAXCAND);
            const int a = g_act[v][i];
            const float* emb = g_e[g_kidx[v][i]];
            for (int c = warp; c < nc; c += 8) {
                unsigned dm = s_dmask[v][c];
                if (!dm) continue;
                int p = s_cand[v][c];
#pragma unroll
                for (int ch = 0; ch < 6; ch++) {
                    int col = ch * 128 + lane * 4;       // 0..764
                    float4 cat;
                    if (col < 256) {
                        cat = *(const float4*)&emb[(size_t)p * DD + col];
                    } else if (col < 512) {
                        cat = *(const float4*)&emb[(size_t)a * DD + (col - 256)];
                    } else {
                        cat = make_float4(0.f, 0.f, 0.f, 0.f);
                        unsigned m = dm;
                        while (m) {
                            int q = __ffs(m) - 1; m &= m - 1;
                            int lk = g_later[v][i][q];
                            float4 e = *(const float4*)&emb[(size_t)lk * DD + (col - 512)];
                            cat.x += e.x; cat.y += e.y; cat.z += e.z; cat.w += e.w;
                        }
                    }
                    float* pir = &g_pi[v][(size_t)p * CC + col];
                    float4 pn = *(float4*)pir;
                    pn.x += cat.x; pn.y += cat.y; pn.z += cat.z; pn.w += cat.w;
                    *(float4*)pir = pn;
                    atomicAdd(&s_delta[v][col + 0], pn.x);
                    atomicAdd(&s_delta[v][col + 1], pn.y);
                    atomicAdd(&s_delta[v][col + 2], pn.z);
                    atomicAdd(&s_delta[v][col + 3], pn.w);
                }
            }
        }
        __syncthreads();

        // Phase D: summary_new = summary_old + delta; persist
        for (int v = 0; v < VV; v++) {
            if (!g_has[v][i]) continue;
            if (t < 192) {
                float4 s = *(float4*)&g_summary[v][t * 4];
                float4 d = *(float4*)&s_delta[v][t * 4];
                s.x += d.x; s.y += d.y; s.z += d.z; s.w += d.w;
                *(float4*)&g_summary[v][t * 4] = s;
                *(float4*)&s_delta[v][t * 4] = s;
            }
        }
        __syncthreads();

        // Phase E: pi[masked] += summary_new
        for (int v = 0; v < VV; v++) {
            if (!g_has[v][i]) continue;
            int nc = min(s_ncand[v], MAXCAND);
            for (int c = warp; c < nc; c += 8) {
                if (!s_dmask[v][c]) continue;
                int p = s_cand[v][c];
#pragma unroll
                for (int ch = 0; ch < 6; ch++) {
                    int col = ch * 128 + lane * 4;
                    float4 s = *(float4*)&s_delta[v][col];
                    float* pir = &g_pi[v][(size_t)p * CC + col];
                    float4 o = *(float4*)pir;
                    o.x += s.x; o.y += s.y; o.z += s.z; o.w += s.w;
                    *(float4*)pir = o;
                }
            }
        }
        return;
    }

    // ============ GEMM: job = bx>>6, tile = bx&63 ============
    const int j = bx >> 6;
    if (j >= g_njobs[i]) return;
    const int k = g_jobs[i][j];
    const int conflict = g_conflict[i];
    if (j == 1 && conflict) {
        // job 1 reads e_{k} = e_{jobs[0]+1}, being written by job 0: wait.
        if (t == 0) { while (ld_acq(&g_done) < 64) {} }
        __syncthreads();
    }
    const int tile = bx & 63;
    const int m0 = (tile >> 2) * 128;    // M = 2048
    const int n0 = (tile & 3) * 64;

    const int wm = warp >> 1;            // 0..3
    const int wn = warp & 1;             // 0..1
    const int g8 = lane >> 2;
    const int tq = lane & 3;

    float acc[2][4][4];
#pragma unroll
    for (int mt = 0; mt < 2; mt++)
#pragma unroll
        for (int nt = 0; nt < 4; nt++)
#pragma unroll
            for (int e = 0; e < 4; e++) acc[mt][nt][e] = 0.f;

    // precompute ldmatrix lane addresses
    uint32_t aaddr[2][2], baddr[2][2];   // [mt|q][h]
    {
        int arow = wm * 32 + (lane & 15);
        int acol = (lane >> 4) * 8;
        aaddr[0][0] = (uint32_t)__cvta_generic_to_shared(&As[0][arow][acol]);
        aaddr[1][0] = (uint32_t)__cvta_generic_to_shared(&As[0][arow + 16][acol]);
        aaddr[0][1] = (uint32_t)__cvta_generic_to_shared(&As[1][arow][acol]);
        aaddr[1][1] = (uint32_t)__cvta_generic_to_shared(&As[1][arow + 16][acol]);
        int brow = wn * 32 + (lane & 7) + ((lane >> 4) << 3);
        int bcol = ((lane >> 3) & 1) * 8;
        baddr[0][0] = (uint32_t)__cvta_generic_to_shared(&Bs[0][brow][bcol]);
        baddr[1][0] = (uint32_t)__cvta_generic_to_shared(&Bs[0][brow + 16][bcol]);
        baddr[0][1] = (uint32_t)__cvta_generic_to_shared(&Bs[1][brow][bcol]);
        baddr[1][1] = (uint32_t)__cvta_generic_to_shared(&Bs[1][brow + 16][bcol]);
    }

    // A loader: thread -> (aq = 8-col group 0..3, ar = row 0..63; rows ar, ar+64)
    const int aq = t & 3;
    const int ar = t >> 2;
    const int bn = t >> 2;
    const int bseg = t & 3;

    const __nv_bfloat16* __restrict__ Xh = g_eh[k];
    const __nv_bfloat16* __restrict__ Xl = g_el[k];
    const __nv_bfloat16* __restrict__ Mh = g_msgh[j];
    const __nv_bfloat16* __restrict__ Ml = g_msgl[j];

    // -------- software-pipelined K loop: register double-buffer --------
    uint4 sh0, sh1, sl0, sl1, swh, swl;
    {
        // prologue: load kt = 0
        int colbase = aq * 8;
        size_t o0 = (size_t)(m0 + ar) * DD + colbase;
        size_t o1 = (size_t)(m0 + ar + 64) * DD + colbase;
        sh0 = *(const uint4*)&Xh[o0];
        sh1 = *(const uint4*)&Xh[o1];
        sl0 = *(const uint4*)&Xl[o0];
        sl1 = *(const uint4*)&Xl[o1];
        size_t woff = (size_t)(n0 + bn) * 512 + bseg * 8;
        swh = *(const uint4*)&g_Wt_hi[woff];
        swl = *(const uint4*)&g_Wt_lo[woff];
    }

    for (int kt = 0; kt < 512; kt += 32) {
        // commit staged tile to smem
        *(uint4*)&As[0][ar][aq * 8]      = sh0;
        *(uint4*)&As[0][ar + 64][aq * 8] = sh1;
        *(uint4*)&As[1][ar][aq * 8]      = sl0;
        *(uint4*)&As[1][ar + 64][aq * 8] = sl1;
        *(uint4*)&Bs[0][bn][bseg * 8] = swh;
        *(uint4*)&Bs[1][bn][bseg * 8] = swl;
        __syncthreads();

        // issue loads for kt+32 (overlapped with compute below)
        int ktn = kt + 32;
        if (ktn < 512) {
            const __nv_bfloat16* Ah = (ktn < 256) ? Xh : Mh;
            const __nv_bfloat16* Al = (ktn < 256) ? Xl : Ml;
            int colbase = (ktn & 255) + aq * 8;
            size_t o0 = (size_t)(m0 + ar) * DD + colbase;
            size_t o1 = (size_t)(m0 + ar + 64) * DD + colbase;
            sh0 = *(const uint4*)&Ah[o0];
            sh1 = *(const uint4*)&Ah[o1];
            sl0 = *(const uint4*)&Al[o0];
            sl1 = *(const uint4*)&Al[o1];
            size_t woff = (size_t)(n0 + bn) * 512 + ktn + bseg * 8;
            swh = *(const uint4*)&g_Wt_hi[woff];
            swl = *(const uint4*)&g_Wt_lo[woff];
        }

#pragma unroll
        for (int sub = 0; sub < 2; sub++) {
            uint32_t off = sub * 32;     // 16 bf16 = 32 bytes
            uint32_t ah0[4], ah1[4], al0[4], al1[4];
            uint32_t bh0[4], bh1[4], bl0[4], bl1[4];
            ldsm4(ah0, aaddr[0][0] + off);
            ldsm4(ah1, aaddr[1][0] + off);
            ldsm4(al0, aaddr[0][1] + off);
            ldsm4(al1, aaddr[1][1] + off);
            ldsm4(bh0, baddr[0][0] + off);
            ldsm4(bh1, baddr[1][0] + off);
            ldsm4(bl0, baddr[0][1] + off);
            ldsm4(bl1, baddr[1][1] + off);
#pragma unroll
            for (int mt = 0; mt < 2; mt++) {
                const uint32_t* ah = mt ? ah1 : ah0;
                const uint32_t* al = mt ? al1 : al0;
                mma16816(acc[mt][0], ah, bh0 + 0);
                mma16816(acc[mt][0], ah, bl0 + 0);
                mma16816(acc[mt][0], al, bh0 + 0);
                mma16816(acc[mt][1], ah, bh0 + 2);
                mma16816(acc[mt][1], ah, bl0 + 2);
                mma16816(acc[mt][1], al, bh0 + 2);
                mma16816(acc[mt][2], ah, bh1 + 0);
                mma16816(acc[mt][2], ah, bl1 + 0);
                mma16816(acc[mt][2], al, bh1 + 0);
                mma16816(acc[mt][3], ah, bh1 + 2);
                mma16816(acc[mt][3], ah, bl1 + 2);
                mma16816(acc[mt][3], al, bh1 + 2);
            }
        }
        __syncthreads();
    }

    // epilogue: + bias, relu, store fp32 + bf16 hi/lo planes into e_{k+1}
    float* O = g_e[k + 1];
    __nv_bfloat16* Oh = g_eh[k + 1];
    __nv_bfloat16* Ol = g_el[k + 1];
#pragma unroll
    for (int mt = 0; mt < 2; mt++) {
        int row = m0 + wm * 32 + mt * 16 + g8;
#pragma unroll
        for (int nt = 0; nt < 4; nt++) {
            int col = n0 + wn * 32 + nt * 8 + tq * 2;
            float b0 = bias[col], b1 = bias[col + 1];
            float2 o0, o1;
            o0.x = fmaxf(acc[mt][nt][0] + b0, 0.f);
            o0.y = fmaxf(acc[mt][nt][1] + b1, 0.f);
            o1.x = fmaxf(acc[mt][nt][2] + b0, 0.f);
            o1.y = fmaxf(acc[mt][nt][3] + b1, 0.f);
            *(float2*)&O[(size_t)row * DD + col] = o0;
            *(float2*)&O[(size_t)(row + 8) * DD + col] = o1;
            __nv_bfloat162 h0 = __floats2bfloat162_rn(o0.x, o0.y);
            __nv_bfloat162 l0 = __floats2bfloat162_rn(o0.x - __bfloat162float(h0.x),
                                                      o0.y - __bfloat162float(h0.y));
            __nv_bfloat162 h1 = __floats2bfloat162_rn(o1.x, o1.y);
            __nv_bfloat162 l1 = __floats2bfloat162_rn(o1.x - __bfloat162float(h1.x),
                                                      o1.y - __bfloat162float(h1.y));
            *(__nv_bfloat162*)&Oh[(size_t)row * DD + col]       = h0;
            *(__nv_bfloat162*)&Ol[(size_t)row * DD + col]       = l0;
            *(__nv_bfloat162*)&Oh[(size_t)(row + 8) * DD + col] = h1;
            *(__nv_bfloat162*)&Ol[(size_t)(row + 8) * DD + col] = l1;
        }
    }
    // conflict gate arrival (job 0 only)
    if (conflict && j == 0) {
        __syncthreads();
        __threadfence();
        if (t == 0) atomicAdd(&g_done, 1u);
    }
}

// ---------------- final: out = pi[0] + pi[1] ----------------
__global__ void sum_out_k(float* __restrict__ out) {
    int t0 = blockIdx.x * blockDim.x + threadIdx.x;
    int stride = gridDim.x * blockDim.x;
    const float4* p0 = (const float4*)g_pi[0];
    const float4* p1 = (const float4*)g_pi[1];
    float4* o4 = (float4*)out;
    int total = NN * CC / 4;
    for (int idx = t0; idx < total; idx += stride) {
        float4 a = p0[idx], b = p1[idx];
        o4[idx] = make_float4(a.x + b.x, a.y + b.y, a.z + b.z, a.w + b.w);
    }
}

// ---------------- launch ----------------
extern "C" void kernel_launch(void* const* d_in, const int* in_sizes, int n_in,
                              void* d_out, int out_size) {
    const float* embeddings = (const float*)d_in[0];
    const float* Wself      = (const float*)d_in[1];
    const float* Wnbr       = (const float*)d_in[2];
    const float* bvec       = (const float*)d_in[3];
    const int*   variants   = (const int*)d_in[4];
    const int*   original   = (const int*)d_in[5];
    const int*   edge_index = (const int*)d_in[6];
    float* out = (float*)d_out;
    int E = in_sizes[6] / 2;

    s1_init_k<<<512, 256>>>(embeddings, Wself, Wnbr);
    s2_prep_count_k<<<129, 256>>>(variants, original, edge_index, E);
    s3_scan_fill_k<<<1, 1024>>>(edge_index, E);

    for (int i = 0; i < LL; i++) {
        q_msg_k<<<dim3(NN, 2), 64>>>(i);
        r_k<<<129, 256>>>(original, bvec, i);
    }

    sum_out_k<<<1024, 256>>>(out);
}

// round 12
// speedup vs baseline: 1.0991x; 1.0500x over previous
#include <cuda_runtime.h>
#include <cuda_bf16.h>
#include <cstdint>

#define NN   2048      // nodes
#define DD   256       // embedding size
#define CC   768       // cat size
#define VV   2         // variants
#define LL   16        // activities per variant
#define EMAX 32768     // 16*N edges
#define MAXCAND 256

// ---------------- scratch (device globals; no allocation allowed) ----------------
// Encoder iterate chain: e_k = encoder^k(embeddings). Both variants index into it.
__device__ float g_e[LL + 1][NN * DD];              // fp32 chain
__device__ __nv_bfloat16 g_eh[LL + 1][NN * DD];     // bf16 hi plane
__device__ __nv_bfloat16 g_el[LL + 1][NN * DD];     // bf16 lo plane
__device__ __nv_bfloat16 g_msgh[2][NN * DD];        // msg hi per job slot
__device__ __nv_bfloat16 g_msgl[2][NN * DD];        // msg lo per job slot
__device__ float g_pi[VV][NN * CC];
__device__ float g_summary[VV][CC];                 // persistent across steps
__device__ int   g_act[VV][LL];
__device__ int   g_later[VV][LL][LL];
__device__ int   g_laterCnt[VV][LL];
__device__ int   g_has[VV][LL];
__device__ int   g_kidx[VV][LL + 1];                // chain index per variant per step
__device__ int   g_jobs[LL][2];                     // distinct k needing e_{k+1} this step
__device__ int   g_njobs[LL];
__device__ int   g_conflict[LL];                    // jobs[1] == jobs[0]+1 (RAW hazard)
__device__ unsigned g_done;                         // job-0 completion counter (conflict gate)
__device__ int   g_csrCnt[NN];
__device__ int   g_csrOff[NN + 1];
__device__ int   g_csrCur[NN];
__device__ int   g_csrSrc[EMAX];
// W stacked [Wself;Wnbr] transposed: [N=256][K=512], bf16 hi/lo split
__device__ __nv_bfloat16 g_Wt_hi[DD * 2 * DD];
__device__ __nv_bfloat16 g_Wt_lo[DD * 2 * DD];

__device__ __forceinline__ unsigned ld_acq(unsigned* p) {
    unsigned v;
    asm volatile("ld.acquire.gpu.u32 %0, [%1];" : "=r"(v) : "l"(p) : "memory");
    return v;
}

// ---------------- S1: init e_0 (fp32 + hi/lo) / pi / csrCnt + W convert ----------------
__global__ void s1_init_k(const float* __restrict__ embeddings,
                          const float* __restrict__ Wself, const float* __restrict__ Wnbr) {
    int t0 = blockIdx.x * blockDim.x + threadIdx.x;
    int stride = gridDim.x * blockDim.x;
    for (int idx = t0; idx < NN * DD; idx += stride) {
        float e = embeddings[idx];
        g_e[0][idx] = e;
        __nv_bfloat16 hi = __float2bfloat16(e);
        __nv_bfloat16 lo = __float2bfloat16(e - __bfloat162float(hi));
        g_eh[0][idx] = hi;
        g_el[0][idx] = lo;
    }
    for (int idx = t0; idx < VV * NN * CC; idx += stride) {
        ((float*)g_pi)[idx] = 0.0f;
    }
    for (int idx = t0; idx < NN; idx += stride) g_csrCnt[idx] = 0;
    for (int idx = t0; idx < DD * 2 * DD; idx += stride) {
        int n = idx >> 9;           // 0..255
        int k = idx & 511;          // 0..511
        float w = (k < DD) ? Wself[k * DD + n] : Wnbr[(k - DD) * DD + n];
        __nv_bfloat16 hi = __float2bfloat16(w);
        __nv_bfloat16 lo = __float2bfloat16(w - __bfloat162float(hi));
        g_Wt_hi[n * 512 + k] = hi;
        g_Wt_lo[n * 512 + k] = lo;
    }
}

// ---------------- S2: csr_count (blocks 0..127) + prep/schedule (block 128) ----------------
__global__ void s2_prep_count_k(const int* __restrict__ variants, const int* __restrict__ adj,
                                const int* __restrict__ ei, int E) {
    int t = threadIdx.x;                 // 256 threads
    if (blockIdx.x < 128) {
        int t0 = blockIdx.x * 256 + t;
        for (int e = t0; e < E; e += 128 * 256) atomicAdd(&g_csrCnt[ei[E + e]], 1);
        return;
    }
    // prep block
    int warp = t >> 5, lane = t & 31;
    for (int pr = warp; pr < VV * LL; pr += 8) {
        int v = pr >> 4, i = pr & 15;
        int a = variants[v * LL + i];
        if (lane == 0) {
            g_act[v][i] = a;
            int cnt = 0;
            for (int j = i + 1; j < LL; j++) {
                int nd = variants[v * LL + j];
                bool dup = false;
                for (int q = 0; q < cnt; q++) if (g_later[v][i][q] == nd) dup = true;
                if (!dup) g_later[v][i][cnt++] = nd;
            }
            g_laterCnt[v][i] = cnt;
        }
        int any = 0;
        for (int p = lane; p < NN; p += 32) any |= (adj[(size_t)a * NN + p] != 0);
        any = __any_sync(0xffffffffu, any);
        if (lane == 0) g_has[v][i] = any;
    }
    for (int idx = t; idx < VV * CC; idx += 256) {
        ((float*)g_summary)[idx] = 0.0f;
    }
    __syncthreads();
    // schedule: chain indices + per-step job list (single thread; trivial size)
    if (t == 0) {
        for (int v = 0; v < VV; v++) {
            int k = 0;
            g_kidx[v][0] = 0;
            for (int i = 0; i < LL; i++) {
                if (g_has[v][i]) k++;
                g_kidx[v][i + 1] = k;
            }
        }
        for (int i = 0; i < LL; i++) {
            int j0 = -1, j1 = -1, n = 0;
            for (int v = 0; v < VV; v++) {
                if (!g_has[v][i]) continue;
                int k = g_kidx[v][i];
                if (n == 0) { j0 = k; n = 1; }
                else if (k != j0) {
                    if (k < j0) { j1 = j0; j0 = k; } else { j1 = k; }
                    n = 2;
                }
            }
            g_jobs[i][0] = j0;
            g_jobs[i][1] = j1;
            g_njobs[i] = n;
            g_conflict[i] = (n == 2 && j1 == j0 + 1) ? 1 : 0;
        }
    }
}

// ---------------- S3: csr scan + fill (single block) ----------------
__global__ void s3_scan_fill_k(const int* __restrict__ ei, int E) {
    __shared__ int s[2][NN];
    int t = threadIdx.x;                 // 1024 threads
    s[0][t] = g_csrCnt[t];
    s[0][t + 1024] = g_csrCnt[t + 1024];
    __syncthreads();
    int src = 0;
    for (int off = 1; off < NN; off <<= 1) {
        int dstb = src ^ 1;
        for (int idx = t; idx < NN; idx += 1024) {
            int val = s[src][idx];
            if (idx >= off) val += s[src][idx - off];
            s[dstb][idx] = val;
        }
        __syncthreads();
        src = dstb;
    }
    for (int idx = t; idx < NN; idx += 1024) {
        int excl = (idx == 0) ? 0 : s[src][idx - 1];
        g_csrOff[idx] = excl;
        g_csrCur[idx] = excl;
    }
    if (t == 0) g_csrOff[NN] = s[src][NN - 1];
    __syncthreads();
    for (int e = t; e < E; e += 1024) {
        int dst = ei[E + e];
        int pos = atomicAdd(&g_csrCur[dst], 1);
        g_csrSrc[pos] = ei[e];
    }
}

// ---------------- Q: msg gather per job, block = (dst, job), 64 threads ----------------
__global__ __launch_bounds__(64) void q_msg_k(int i) {
    const int p = blockIdx.x, j = blockIdx.y;
    if (p == 0 && j == 0 && threadIdx.x == 0) g_done = 0;   // reset conflict gate for R(i)
    if (j >= g_njobs[i]) return;
    const int k = g_jobs[i][j];

    __shared__ int sidx[64];
    const float4* __restrict__ emb4 = (const float4*)g_e[k];
    const int t = threadIdx.x;           // 64 threads x float4 = 256 cols
    float4 acc = make_float4(0.f, 0.f, 0.f, 0.f);
    const int s0 = g_csrOff[p];
    const int deg = g_csrOff[p + 1] - s0;

    for (int base = 0; base < deg; base += 64) {
        int chunk = min(64, deg - base);
        if (base) __syncthreads();
        if (t < chunk) sidx[t] = g_csrSrc[s0 + base + t];
        __syncthreads();
#pragma unroll 8
        for (int jj = 0; jj < chunk; jj++) {
            float4 e = __ldg(&emb4[(size_t)sidx[jj] * (DD / 4) + t]);
            acc.x += e.x; acc.y += e.y; acc.z += e.z; acc.w += e.w;
        }
    }
    __nv_bfloat162 h0 = __floats2bfloat162_rn(acc.x, acc.y);
    __nv_bfloat162 h1 = __floats2bfloat162_rn(acc.z, acc.w);
    __nv_bfloat162 l0 = __floats2bfloat162_rn(acc.x - __bfloat162float(h0.x),
                                              acc.y - __bfloat162float(h0.y));
    __nv_bfloat162 l1 = __floats2bfloat162_rn(acc.z - __bfloat162float(h1.x),
                                              acc.w - __bfloat162float(h1.y));
    size_t off = (size_t)p * DD + t * 4;
    *(__nv_bfloat162*)&g_msgh[j][off]     = h0;
    *(__nv_bfloat162*)&g_msgh[j][off + 2] = h1;
    *(__nv_bfloat162*)&g_msgl[j][off]     = l0;
    *(__nv_bfloat162*)&g_msgl[j][off + 2] = l1;
}

// ---------------- GEMM helpers ----------------
#define SA 40
#define SB 40

__device__ __forceinline__ void mma16816(float* c, const uint32_t* a, const uint32_t* b) {
    asm volatile(
        "mma.sync.aligned.m16n8k16.row.col.f32.bf16.bf16.f32 "
        "{%0,%1,%2,%3}, {%4,%5,%6,%7}, {%8,%9}, {%0,%1,%2,%3};"
        : "+f"(c[0]), "+f"(c[1]), "+f"(c[2]), "+f"(c[3])
        : "r"(a[0]), "r"(a[1]), "r"(a[2]), "r"(a[3]), "r"(b[0]), "r"(b[1]));
}
__device__ __forceinline__ void ldsm4(uint32_t* r, uint32_t addr) {
    asm volatile("ldmatrix.sync.aligned.m8n8.x4.shared.b16 {%0,%1,%2,%3}, [%4];"
        : "=r"(r[0]), "=r"(r[1]), "=r"(r[2]), "=r"(r[3]) : "r"(addr));
}

// ---------------- R: stepA/BC (block 0) + GEMM jobs (blocks 1..256), 256 threads ----------------
// GEMM tiling: BM=128, BN=32 -> 16 x 8 = 128 blocks per job, 2 jobs max.
__global__ __launch_bounds__(256) void r_k(const int* __restrict__ adj,
                                           const float* __restrict__ bias, int i) {
    const int bx = blockIdx.x;
    const int t = threadIdx.x;
    const int lane = t & 31;
    const int warp = t >> 5;

    __shared__ __align__(16) __nv_bfloat16 As[2][128][SA];   // [hi/lo]
    __shared__ __align__(16) __nv_bfloat16 Bs[2][32][SB];
    __shared__ float s_delta[VV][CC];
    __shared__ int s_cand[VV][MAXCAND];
    __shared__ unsigned s_dmask[VV][MAXCAND];
    __shared__ int s_ncand[VV];

    if (bx == 0) {
        // ============ stepA + stepBC, whole step, one block ============
        for (int idx = t; idx < VV * CC; idx += 256) ((float*)s_delta)[idx] = 0.f;
        if (t < VV) s_ncand[t] = 0;
        __syncthreads();

        // Phase A: candidate scan (followers of a) — adj only
        for (int v = 0; v < VV; v++) {
            if (!g_has[v][i]) continue;
            const int a = g_act[v][i];
            for (int p = t; p < NN; p += 256) {
                if (adj[(size_t)a * NN + p] != 0) {
                    int id = atomicAdd(&s_ncand[v], 1);
                    if (id < MAXCAND) s_cand[v][id] = p;
                }
            }
        }
        __syncthreads();

        // Phase B: dest-set probe, warp per candidate — adj only
        for (int v = 0; v < VV; v++) {
            if (!g_has[v][i]) continue;
            int nc = min(s_ncand[v], MAXCAND);
            const int cnt = g_laterCnt[v][i];
            for (int c = warp; c < nc; c += 8) {
                int p = s_cand[v][c];
                int hit = (lane < cnt) ? (adj[(size_t)p * NN + g_later[v][i][lane]] != 0) : 0;
                unsigned dm = __ballot_sync(0xffffffffu, hit);
                if (lane == 0) s_dmask[v][c] = dm;
            }
        }
        __syncthreads();

        // Conflict gate: if job 0 writes e_{k} that one variant reads below, wait it out.
        if (g_conflict[i]) {
            if (t == 0) { while (ld_acq(&g_done) < 128) {} }
            __syncthreads();
        }

        // Phase C: pi[p] += cat; delta += pi_new  (warp per masked candidate)
        for (int v = 0; v < VV; v++) {
            if (!g_has[v][i]) continue;
            int nc = min(s_ncand[v], MAXCAND);
            const int a = g_act[v][i];
            const float* emb = g_e[g_kidx[v][i]];
            for (int c = warp; c < nc; c += 8) {
                unsigned dm = s_dmask[v][c];
                if (!dm) continue;
                int p = s_cand[v][c];
#pragma unroll
                for (int ch = 0; ch < 6; ch++) {
                    int col = ch * 128 + lane * 4;       // 0..764
                    float4 cat;
                    if (col < 256) {
                        cat = *(const float4*)&emb[(size_t)p * DD + col];
                    } else if (col < 512) {
                        cat = *(const float4*)&emb[(size_t)a * DD + (col - 256)];
                    } else {
                        cat = make_float4(0.f, 0.f, 0.f, 0.f);
                        unsigned m = dm;
                        while (m) {
                            int q = __ffs(m) - 1; m &= m - 1;
                            int lk = g_later[v][i][q];
                            float4 e = *(const float4*)&emb[(size_t)lk * DD + (col - 512)];
                            cat.x += e.x; cat.y += e.y; cat.z += e.z; cat.w += e.w;
                        }
                    }
                    float* pir = &g_pi[v][(size_t)p * CC + col];
                    float4 pn = *(float4*)pir;
                    pn.x += cat.x; pn.y += cat.y; pn.z += cat.z; pn.w += cat.w;
                    *(float4*)pir = pn;
                    atomicAdd(&s_delta[v][col + 0], pn.x);
                    atomicAdd(&s_delta[v][col + 1], pn.y);
                    atomicAdd(&s_delta[v][col + 2], pn.z);
                    atomicAdd(&s_delta[v][col + 3], pn.w);
                }
            }
        }
        __syncthreads();

        // Phase D: summary_new = summary_old + delta; persist
        for (int v = 0; v < VV; v++) {
            if (!g_has[v][i]) continue;
            if (t < 192) {
                float4 s = *(float4*)&g_summary[v][t * 4];
                float4 d = *(float4*)&s_delta[v][t * 4];
                s.x += d.x; s.y += d.y; s.z += d.z; s.w += d.w;
                *(float4*)&g_summary[v][t * 4] = s;
                *(float4*)&s_delta[v][t * 4] = s;
            }
        }
        __syncthreads();

        // Phase E: pi[masked] += summary_new
        for (int v = 0; v < VV; v++) {
            if (!g_has[v][i]) continue;
            int nc = min(s_ncand[v], MAXCAND);
            for (int c = warp; c < nc; c += 8) {
                if (!s_dmask[v][c]) continue;
                int p = s_cand[v][c];
#pragma unroll
                for (int ch = 0; ch < 6; ch++) {
                    int col = ch * 128 + lane * 4;
                    float4 s = *(float4*)&s_delta[v][col];
                    float* pir = &g_pi[v][(size_t)p * CC + col];
                    float4 o = *(float4*)pir;
                    o.x += s.x; o.y += s.y; o.z += s.z; o.w += s.w;
                    *(float4*)pir = o;
                }
            }
        }
        return;
    }

    // ============ GEMM: gb = bx-1; job = gb>>7, tile = gb&127 ============
    const int gb = bx - 1;
    const int j = gb >> 7;
    if (j >= g_njobs[i]) return;
    const int k = g_jobs[i][j];
    const int conflict = g_conflict[i];
    if (j == 1 && conflict) {
        // job 1 reads e_{k} = e_{jobs[0]+1}, being written by job 0: wait.
        if (t == 0) { while (ld_acq(&g_done) < 128) {} }
        __syncthreads();
    }
    const int tile = gb & 127;
    const int m0 = (tile >> 3) * 128;    // 16 m-tiles, M = 2048
    const int n0 = (tile & 7) * 32;      // 8 n-tiles, N = 256

    const int wm = warp >> 1;            // 0..3 (M offset 32 each)
    const int wn = warp & 1;             // 0..1 (N offset 16 each)
    const int g8 = lane >> 2;
    const int tq = lane & 3;

    float acc[2][2][4];
#pragma unroll
    for (int mt = 0; mt < 2; mt++)
#pragma unroll
        for (int nt = 0; nt < 2; nt++)
#pragma unroll
            for (int e = 0; e < 4; e++) acc[mt][nt][e] = 0.f;

    // precompute ldmatrix lane addresses
    uint32_t aaddr[2][2], baddr[2];      // A: [mt][h]; B: [h]
    {
        int arow = wm * 32 + (lane & 15);
        int acol = (lane >> 4) * 8;
        aaddr[0][0] = (uint32_t)__cvta_generic_to_shared(&As[0][arow][acol]);
        aaddr[1][0] = (uint32_t)__cvta_generic_to_shared(&As[0][arow + 16][acol]);
        aaddr[0][1] = (uint32_t)__cvta_generic_to_shared(&As[1][arow][acol]);
        aaddr[1][1] = (uint32_t)__cvta_generic_to_shared(&As[1][arow + 16][acol]);
        int brow = wn * 16 + (lane & 7) + ((lane >> 4) << 3);
        int bcol = ((lane >> 3) & 1) * 8;
        baddr[0] = (uint32_t)__cvta_generic_to_shared(&Bs[0][brow][bcol]);
        baddr[1] = (uint32_t)__cvta_generic_to_shared(&Bs[1][brow][bcol]);
    }

    // A loader: aq = 8-col group 0..3, ar = row 0..63; rows ar, ar+64
    const int aq = t & 3;
    const int ar = t >> 2;
    // B loader: bn = n row 0..31, bseg = 4-col group 0..7
    const int bn = t >> 3;
    const int bseg = t & 7;

    const __nv_bfloat16* __restrict__ Xh = g_eh[k];
    const __nv_bfloat16* __restrict__ Xl = g_el[k];
    const __nv_bfloat16* __restrict__ Mh = g_msgh[j];
    const __nv_bfloat16* __restrict__ Ml = g_msgl[j];

    // -------- software-pipelined K loop: register double-buffer --------
    uint4 sh0, sh1, sl0, sl1;
    uint2 swh, swl;
    {
        // prologue: load kt = 0
        int colbase = aq * 8;
        size_t o0 = (size_t)(m0 + ar) * DD + colbase;
        size_t o1 = (size_t)(m0 + ar + 64) * DD + colbase;
        sh0 = *(const uint4*)&Xh[o0];
        sh1 = *(const uint4*)&Xh[o1];
        sl0 = *(const uint4*)&Xl[o0];
        sl1 = *(const uint4*)&Xl[o1];
        size_t woff = (size_t)(n0 + bn) * 512 + bseg * 4;
        swh = *(const uint2*)&g_Wt_hi[woff];
        swl = *(const uint2*)&g_Wt_lo[woff];
    }

    for (int kt = 0; kt < 512; kt += 32) {
        // commit staged tile to smem
        *(uint4*)&As[0][ar][aq * 8]      = sh0;
        *(uint4*)&As[0][ar + 64][aq * 8] = sh1;
        *(uint4*)&As[1][ar][aq * 8]      = sl0;
        *(uint4*)&As[1][ar + 64][aq * 8] = sl1;
        *(uint2*)&Bs[0][bn][bseg * 4] = swh;
        *(uint2*)&Bs[1][bn][bseg * 4] = swl;
        __syncthreads();

        // issue loads for kt+32 (overlapped with compute below)
        int ktn = kt + 32;
        if (ktn < 512) {
            const __nv_bfloat16* Ah = (ktn < 256) ? Xh : Mh;
            const __nv_bfloat16* Al = (ktn < 256) ? Xl : Ml;
            int colbase = (ktn & 255) + aq * 8;
            size_t o0 = (size_t)(m0 + ar) * DD + colbase;
            size_t o1 = (size_t)(m0 + ar + 64) * DD + colbase;
            sh0 = *(const uint4*)&Ah[o0];
            sh1 = *(const uint4*)&Ah[o1];
            sl0 = *(const uint4*)&Al[o0];
            sl1 = *(const uint4*)&Al[o1];
            size_t woff = (size_t)(n0 + bn) * 512 + ktn + bseg * 4;
            swh = *(const uint2*)&g_Wt_hi[woff];
            swl = *(const uint2*)&g_Wt_lo[woff];
        }

#pragma unroll
        for (int sub = 0; sub < 2; sub++) {
            uint32_t off = sub * 32;     // 16 bf16 = 32 bytes
            uint32_t ah0[4], ah1[4], al0[4], al1[4];
            uint32_t bh[4], bl[4];
            ldsm4(ah0, aaddr[0][0] + off);
            ldsm4(ah1, aaddr[1][0] + off);
            ldsm4(al0, aaddr[0][1] + off);
            ldsm4(al1, aaddr[1][1] + off);
            ldsm4(bh, baddr[0] + off);
            ldsm4(bl, baddr[1] + off);
#pragma unroll
            for (int mt = 0; mt < 2; mt++) {
                const uint32_t* ah = mt ? ah1 : ah0;
                const uint32_t* al = mt ? al1 : al0;
                mma16816(acc[mt][0], ah, bh + 0);
                mma16816(acc[mt][0], ah, bl + 0);
                mma16816(acc[mt][0], al, bh + 0);
                mma16816(acc[mt][1], ah, bh + 2);
                mma16816(acc[mt][1], ah, bl + 2);
                mma16816(acc[mt][1], al, bh + 2);
            }
        }
        __syncthreads();
    }

    // epilogue: + bias, relu, store fp32 + bf16 hi/lo planes into e_{k+1}
    float* O = g_e[k + 1];
    __nv_bfloat16* Oh = g_eh[k + 1];
    __nv_bfloat16* Ol = g_el[k + 1];
#pragma unroll
    for (int mt = 0; mt < 2; mt++) {
        int row = m0 + wm * 32 + mt * 16 + g8;
#pragma unroll
        for (int nt = 0; nt < 2; nt++) {
            int col = n0 + wn * 16 + nt * 8 + tq * 2;
            float b0 = bias[col], b1 = bias[col + 1];
            float2 o0, o1;
            o0.x = fmaxf(acc[mt][nt][0] + b0, 0.f);
            o0.y = fmaxf(acc[mt][nt][1] + b1, 0.f);
            o1.x = fmaxf(acc[mt][nt][2] + b0, 0.f);
            o1.y = fmaxf(acc[mt][nt][3] + b1, 0.f);
            *(float2*)&O[(size_t)row * DD + col] = o0;
            *(float2*)&O[(size_t)(row + 8) * DD + col] = o1;
            __nv_bfloat162 h0 = __floats2bfloat162_rn(o0.x, o0.y);
            __nv_bfloat162 l0 = __floats2bfloat162_rn(o0.x - __bfloat162float(h0.x),
                                                      o0.y - __bfloat162float(h0.y));
            __nv_bfloat162 h1 = __floats2bfloat162_rn(o1.x, o1.y);
            __nv_bfloat162 l1 = __floats2bfloat162_rn(o1.x - __bfloat162float(h1.x),
                                                      o1.y - __bfloat162float(h1.y));
            *(__nv_bfloat162*)&Oh[(size_t)row * DD + col]       = h0;
            *(__nv_bfloat162*)&Ol[(size_t)row * DD + col]       = l0;
            *(__nv_bfloat162*)&Oh[(size_t)(row + 8) * DD + col] = h1;
            *(__nv_bfloat162*)&Ol[(size_t)(row + 8) * DD + col] = l1;
        }
    }
    // conflict gate arrival (job 0 only)
    if (conflict && j == 0) {
        __syncthreads();
        __threadfence();
        if (t == 0) atomicAdd(&g_done, 1u);
    }
}

// ---------------- final: out = pi[0] + pi[1] ----------------
__global__ void sum_out_k(float* __restrict__ out) {
    int t0 = blockIdx.x * blockDim.x + threadIdx.x;
    int stride = gridDim.x * blockDim.x;
    const float4* p0 = (const float4*)g_pi[0];
    const float4* p1 = (const float4*)g_pi[1];
    float4* o4 = (float4*)out;
    int total = NN * CC / 4;
    for (int idx = t0; idx < total; idx += stride) {
        float4 a = p0[idx], b = p1[idx];
        o4[idx] = make_float4(a.x + b.x, a.y + b.y, a.z + b.z, a.w + b.w);
    }
}

// ---------------- launch ----------------
extern "C" void kernel_launch(void* const* d_in, const int* in_sizes, int n_in,
                              void* d_out, int out_size) {
    const float* embeddings = (const float*)d_in[0];
    const float* Wself      = (const float*)d_in[1];
    const float* Wnbr       = (const float*)d_in[2];
    const float* bvec       = (const float*)d_in[3];
    const int*   variants   = (const int*)d_in[4];
    const int*   original   = (const int*)d_in[5];
    const int*   edge_index = (const int*)d_in[6];
    float* out = (float*)d_out;
    int E = in_sizes[6] / 2;

    s1_init_k<<<512, 256>>>(embeddings, Wself, Wnbr);
    s2_prep_count_k<<<129, 256>>>(variants, original, edge_index, E);
    s3_scan_fill_k<<<1, 1024>>>(edge_index, E);

    for (int i = 0; i < LL; i++) {
        q_msg_k<<<dim3(NN, 2), 64>>>(i);
        r_k<<<257, 256>>>(original, bvec, i);
    }

    sum_out_k<<<1024, 256>>>(out);
}

// round 13
// speedup vs baseline: 1.1031x; 1.0036x over previous
#include <cuda_runtime.h>
#include <cuda_bf16.h>
#include <cstdint>

#define NN   2048      // nodes
#define DD   256       // embedding size
#define CC   768       // cat size
#define VV   2         // variants
#define LL   16        // activities per variant
#define EMAX 32768     // 16*N edges
#define MAXCAND 256

// ---------------- scratch (device globals; no allocation allowed) ----------------
// Encoder iterate chain: e_k = encoder^k(embeddings). Both variants index into it.
__device__ float g_e[LL + 1][NN * DD];              // fp32 chain
__device__ __nv_bfloat16 g_eh[LL + 1][NN * DD];     // bf16 hi plane
__device__ __nv_bfloat16 g_el[LL + 1][NN * DD];     // bf16 lo plane
__device__ __nv_bfloat16 g_msgh[2][NN * DD];        // msg hi per job slot
__device__ __nv_bfloat16 g_msgl[2][NN * DD];        // msg lo per job slot
__device__ float g_pi[VV][NN * CC];
__device__ float g_summary[VV][CC];                 // persistent across steps
__device__ int   g_act[VV][LL];
__device__ int   g_later[VV][LL][LL];
__device__ int   g_laterCnt[VV][LL];
__device__ int   g_has[VV][LL];
__device__ int   g_kidx[VV][LL + 1];                // chain index per variant per step
__device__ int   g_jobs[LL][2];                     // distinct k needing e_{k+1} this step
__device__ int   g_njobs[LL];
__device__ int   g_conflict[LL];                    // jobs[1] == jobs[0]+1 (RAW hazard)
__device__ unsigned g_done;                         // job-0 completion counter (conflict gate)
__device__ int   g_csrCnt[NN];
__device__ int   g_csrOff[NN + 1];
__device__ int   g_csrCur[NN];
__device__ int   g_csrSrc[EMAX];
// W stacked [Wself;Wnbr] transposed: [N=256][K=512], bf16 hi/lo split
__device__ __nv_bfloat16 g_Wt_hi[DD * 2 * DD];
__device__ __nv_bfloat16 g_Wt_lo[DD * 2 * DD];

__device__ __forceinline__ unsigned ld_acq(unsigned* p) {
    unsigned v;
    asm volatile("ld.acquire.gpu.u32 %0, [%1];" : "=r"(v) : "l"(p) : "memory");
    return v;
}

// ---------------- S1: init e_0 (fp32 + hi/lo) / pi / csrCnt + W convert ----------------
__global__ void s1_init_k(const float* __restrict__ embeddings,
                          const float* __restrict__ Wself, const float* __restrict__ Wnbr) {
    int t0 = blockIdx.x * blockDim.x + threadIdx.x;
    int stride = gridDim.x * blockDim.x;
    for (int idx = t0; idx < NN * DD; idx += stride) {
        float e = embeddings[idx];
        g_e[0][idx] = e;
        __nv_bfloat16 hi = __float2bfloat16(e);
        __nv_bfloat16 lo = __float2bfloat16(e - __bfloat162float(hi));
        g_eh[0][idx] = hi;
        g_el[0][idx] = lo;
    }
    for (int idx = t0; idx < VV * NN * CC; idx += stride) {
        ((float*)g_pi)[idx] = 0.0f;
    }
    for (int idx = t0; idx < NN; idx += stride) g_csrCnt[idx] = 0;
    for (int idx = t0; idx < DD * 2 * DD; idx += stride) {
        int n = idx >> 9;           // 0..255
        int k = idx & 511;          // 0..511
        float w = (k < DD) ? Wself[k * DD + n] : Wnbr[(k - DD) * DD + n];
        __nv_bfloat16 hi = __float2bfloat16(w);
        __nv_bfloat16 lo = __float2bfloat16(w - __bfloat162float(hi));
        g_Wt_hi[n * 512 + k] = hi;
        g_Wt_lo[n * 512 + k] = lo;
    }
}

// ---------------- S2: csr_count (blocks 0..127) + prep/schedule (block 128) ----------------
__global__ void s2_prep_count_k(const int* __restrict__ variants, const int* __restrict__ adj,
                                const int* __restrict__ ei, int E) {
    int t = threadIdx.x;                 // 256 threads
    if (blockIdx.x < 128) {
        int t0 = blockIdx.x * 256 + t;
        for (int e = t0; e < E; e += 128 * 256) atomicAdd(&g_csrCnt[ei[E + e]], 1);
        return;
    }
    // prep block
    int warp = t >> 5, lane = t & 31;
    for (int pr = warp; pr < VV * LL; pr += 8) {
        int v = pr >> 4, i = pr & 15;
        int a = variants[v * LL + i];
        if (lane == 0) {
            g_act[v][i] = a;
            int cnt = 0;
            for (int j = i + 1; j < LL; j++) {
                int nd = variants[v * LL + j];
                bool dup = false;
                for (int q = 0; q < cnt; q++) if (g_later[v][i][q] == nd) dup = true;
                if (!dup) g_later[v][i][cnt++] = nd;
            }
            g_laterCnt[v][i] = cnt;
        }
        int any = 0;
        for (int p = lane; p < NN; p += 32) any |= (adj[(size_t)a * NN + p] != 0);
        any = __any_sync(0xffffffffu, any);
        if (lane == 0) g_has[v][i] = any;
    }
    for (int idx = t; idx < VV * CC; idx += 256) {
        ((float*)g_summary)[idx] = 0.0f;
    }
    __syncthreads();
    // schedule: chain indices + per-step job list (single thread; trivial size)
    if (t == 0) {
        for (int v = 0; v < VV; v++) {
            int k = 0;
            g_kidx[v][0] = 0;
            for (int i = 0; i < LL; i++) {
                if (g_has[v][i]) k++;
                g_kidx[v][i + 1] = k;
            }
        }
        for (int i = 0; i < LL; i++) {
            int j0 = -1, j1 = -1, n = 0;
            for (int v = 0; v < VV; v++) {
                if (!g_has[v][i]) continue;
                int k = g_kidx[v][i];
                if (n == 0) { j0 = k; n = 1; }
                else if (k != j0) {
                    if (k < j0) { j1 = j0; j0 = k; } else { j1 = k; }
                    n = 2;
                }
            }
            g_jobs[i][0] = j0;
            g_jobs[i][1] = j1;
            g_njobs[i] = n;
            g_conflict[i] = (n == 2 && j1 == j0 + 1) ? 1 : 0;
        }
    }
}

// ---------------- S3: csr scan + fill (single block) ----------------
__global__ void s3_scan_fill_k(const int* __restrict__ ei, int E) {
    __shared__ int s[2][NN];
    int t = threadIdx.x;                 // 1024 threads
    s[0][t] = g_csrCnt[t];
    s[0][t + 1024] = g_csrCnt[t + 1024];
    __syncthreads();
    int src = 0;
    for (int off = 1; off < NN; off <<= 1) {
        int dstb = src ^ 1;
        for (int idx = t; idx < NN; idx += 1024) {
            int val = s[src][idx];
            if (idx >= off) val += s[src][idx - off];
            s[dstb][idx] = val;
        }
        __syncthreads();
        src = dstb;
    }
    for (int idx = t; idx < NN; idx += 1024) {
        int excl = (idx == 0) ? 0 : s[src][idx - 1];
        g_csrOff[idx] = excl;
        g_csrCur[idx] = excl;
    }
    if (t == 0) g_csrOff[NN] = s[src][NN - 1];
    __syncthreads();
    for (int e = t; e < E; e += 1024) {
        int dst = ei[E + e];
        int pos = atomicAdd(&g_csrCur[dst], 1);
        g_csrSrc[pos] = ei[e];
    }
}

// ---------------- Q: msg gather per job, block = (dst, job), 64 threads ----------------
__global__ __launch_bounds__(64) void q_msg_k(int i) {
    const int p = blockIdx.x, j = blockIdx.y;
    if (p == 0 && j == 0 && threadIdx.x == 0) g_done = 0;   // reset conflict gate for R(i)
    if (j >= g_njobs[i]) return;
    const int k = g_jobs[i][j];

    __shared__ int sidx[64];
    const float4* __restrict__ emb4 = (const float4*)g_e[k];
    const int t = threadIdx.x;           // 64 threads x float4 = 256 cols
    float4 acc = make_float4(0.f, 0.f, 0.f, 0.f);
    const int s0 = g_csrOff[p];
    const int deg = g_csrOff[p + 1] - s0;

    for (int base = 0; base < deg; base += 64) {
        int chunk = min(64, deg - base);
        if (base) __syncthreads();
        if (t < chunk) sidx[t] = g_csrSrc[s0 + base + t];
        __syncthreads();
#pragma unroll 8
        for (int jj = 0; jj < chunk; jj++) {
            float4 e = __ldg(&emb4[(size_t)sidx[jj] * (DD / 4) + t]);
            acc.x += e.x; acc.y += e.y; acc.z += e.z; acc.w += e.w;
        }
    }
    __nv_bfloat162 h0 = __floats2bfloat162_rn(acc.x, acc.y);
    __nv_bfloat162 h1 = __floats2bfloat162_rn(acc.z, acc.w);
    __nv_bfloat162 l0 = __floats2bfloat162_rn(acc.x - __bfloat162float(h0.x),
                                              acc.y - __bfloat162float(h0.y));
    __nv_bfloat162 l1 = __floats2bfloat162_rn(acc.z - __bfloat162float(h1.x),
                                              acc.w - __bfloat162float(h1.y));
    size_t off = (size_t)p * DD + t * 4;
    *(__nv_bfloat162*)&g_msgh[j][off]     = h0;
    *(__nv_bfloat162*)&g_msgh[j][off + 2] = h1;
    *(__nv_bfloat162*)&g_msgl[j][off]     = l0;
    *(__nv_bfloat162*)&g_msgl[j][off + 2] = l1;
}

// ---------------- GEMM helpers ----------------
#define SA 40
#define SB 40

__device__ __forceinline__ void mma16816(float* c, const uint32_t* a, const uint32_t* b) {
    asm volatile(
        "mma.sync.aligned.m16n8k16.row.col.f32.bf16.bf16.f32 "
        "{%0,%1,%2,%3}, {%4,%5,%6,%7}, {%8,%9}, {%0,%1,%2,%3};"
        : "+f"(c[0]), "+f"(c[1]), "+f"(c[2]), "+f"(c[3])
        : "r"(a[0]), "r"(a[1]), "r"(a[2]), "r"(a[3]), "r"(b[0]), "r"(b[1]));
}
__device__ __forceinline__ void ldsm4(uint32_t* r, uint32_t addr) {
    asm volatile("ldmatrix.sync.aligned.m8n8.x4.shared.b16 {%0,%1,%2,%3}, [%4];"
        : "=r"(r[0]), "=r"(r[1]), "=r"(r[2]), "=r"(r[3]) : "r"(addr));
}

// ---------------- R: stepA/BC (block 0) + GEMM jobs (blocks 1..256), 256 threads ----------------
// GEMM tiling: BM=128, BN=32 -> 16 x 8 = 128 blocks per job, 2 jobs max.
__global__ __launch_bounds__(256) void r_k(const int* __restrict__ adj,
                                           const float* __restrict__ bias, int i) {
    const int bx = blockIdx.x;
    const int t = threadIdx.x;
    const int lane = t & 31;
    const int warp = t >> 5;

    __shared__ __align__(16) __nv_bfloat16 As[2][128][SA];   // [hi/lo]
    __shared__ __align__(16) __nv_bfloat16 Bs[2][32][SB];
    __shared__ float s_delta[VV][CC];
    __shared__ int s_cand[VV][MAXCAND];
    __shared__ unsigned s_dmask[VV][MAXCAND];
    __shared__ int s_ncand[VV];

    if (bx == 0) {
        // ============ stepA + stepBC, whole step, one block ============
        for (int idx = t; idx < VV * CC; idx += 256) ((float*)s_delta)[idx] = 0.f;
        if (t < VV) s_ncand[t] = 0;
        __syncthreads();

        // Phase A: candidate scan (followers of a) — adj only
        for (int v = 0; v < VV; v++) {
            if (!g_has[v][i]) continue;
            const int a = g_act[v][i];
            for (int p = t; p < NN; p += 256) {
                if (adj[(size_t)a * NN + p] != 0) {
                    int id = atomicAdd(&s_ncand[v], 1);
                    if (id < MAXCAND) s_cand[v][id] = p;
                }
            }
        }
        __syncthreads();

        // Phase B: dest-set probe, warp per candidate — adj only
        for (int v = 0; v < VV; v++) {
            if (!g_has[v][i]) continue;
            int nc = min(s_ncand[v], MAXCAND);
            const int cnt = g_laterCnt[v][i];
            for (int c = warp; c < nc; c += 8) {
                int p = s_cand[v][c];
                int hit = (lane < cnt) ? (adj[(size_t)p * NN + g_later[v][i][lane]] != 0) : 0;
                unsigned dm = __ballot_sync(0xffffffffu, hit);
                if (lane == 0) s_dmask[v][c] = dm;
            }
        }
        __syncthreads();

        // Conflict gate: if job 0 writes e_{k} that one variant reads below, wait it out.
        if (g_conflict[i]) {
            if (t == 0) { while (ld_acq(&g_done) < 128) {} }
            __syncthreads();
        }

        // Phase C: pi[p] += cat; delta += pi_new  (warp per masked candidate)
        for (int v = 0; v < VV; v++) {
            if (!g_has[v][i]) continue;
            int nc = min(s_ncand[v], MAXCAND);
            const int a = g_act[v][i];
            const float* emb = g_e[g_kidx[v][i]];
            for (int c = warp; c < nc; c += 8) {
                unsigned dm = s_dmask[v][c];
                if (!dm) continue;
                int p = s_cand[v][c];
#pragma unroll
                for (int ch = 0; ch < 6; ch++) {
                    int col = ch * 128 + lane * 4;       // 0..764
                    float4 cat;
                    if (col < 256) {
                        cat = *(const float4*)&emb[(size_t)p * DD + col];
                    } else if (col < 512) {
                        cat = *(const float4*)&emb[(size_t)a * DD + (col - 256)];
                    } else {
                        cat = make_float4(0.f, 0.f, 0.f, 0.f);
                        unsigned m = dm;
                        while (m) {
                            int q = __ffs(m) - 1; m &= m - 1;
                            int lk = g_later[v][i][q];
                            float4 e = *(const float4*)&emb[(size_t)lk * DD + (col - 512)];
                            cat.x += e.x; cat.y += e.y; cat.z += e.z; cat.w += e.w;
                        }
                    }
                    float* pir = &g_pi[v][(size_t)p * CC + col];
                    float4 pn = *(float4*)pir;
                    pn.x += cat.x; pn.y += cat.y; pn.z += cat.z; pn.w += cat.w;
                    *(float4*)pir = pn;
                    atomicAdd(&s_delta[v][col + 0], pn.x);
                    atomicAdd(&s_delta[v][col + 1], pn.y);
                    atomicAdd(&s_delta[v][col + 2], pn.z);
                    atomicAdd(&s_delta[v][col + 3], pn.w);
                }
            }
        }
        __syncthreads();

        // Phase D: summary_new = summary_old + delta; persist
        for (int v = 0; v < VV; v++) {
            if (!g_has[v][i]) continue;
            if (t < 192) {
                float4 s = *(float4*)&g_summary[v][t * 4];
                float4 d = *(float4*)&s_delta[v][t * 4];
                s.x += d.x; s.y += d.y; s.z += d.z; s.w += d.w;
                *(float4*)&g_summary[v][t * 4] = s;
                *(float4*)&s_delta[v][t * 4] = s;
            }
        }
        __syncthreads();

        // Phase E: pi[masked] += summary_new
        for (int v = 0; v < VV; v++) {
            if (!g_has[v][i]) continue;
            int nc = min(s_ncand[v], MAXCAND);
            for (int c = warp; c < nc; c += 8) {
                if (!s_dmask[v][c]) continue;
                int p = s_cand[v][c];
#pragma unroll
                for (int ch = 0; ch < 6; ch++) {
                    int col = ch * 128 + lane * 4;
                    float4 s = *(float4*)&s_delta[v][col];
                    float* pir = &g_pi[v][(size_t)p * CC + col];
                    float4 o = *(float4*)pir;
                    o.x += s.x; o.y += s.y; o.z += s.z; o.w += s.w;
                    *(float4*)pir = o;
                }
            }
        }
        return;
    }

    // ============ GEMM: gb = bx-1; job = gb>>7, tile = gb&127 ============
    const int gb = bx - 1;
    const int j = gb >> 7;
    if (j >= g_njobs[i]) return;
    const int k = g_jobs[i][j];
    const int conflict = g_conflict[i];
    if (j == 1 && conflict) {
        // job 1 reads e_{k} = e_{jobs[0]+1}, being written by job 0: wait.
        if (t == 0) { while (ld_acq(&g_done) < 128) {} }
        __syncthreads();
    }
    const int tile = gb & 127;
    const int m0 = (tile >> 3) * 128;    // 16 m-tiles, M = 2048
    const int n0 = (tile & 7) * 32;      // 8 n-tiles, N = 256

    const int wm = warp >> 1;            // 0..3 (M offset 32 each)
    const int wn = warp & 1;             // 0..1 (N offset 16 each)
    const int g8 = lane >> 2;
    const int tq = lane & 3;

    float acc[2][2][4];
#pragma unroll
    for (int mt = 0; mt < 2; mt++)
#pragma unroll
        for (int nt = 0; nt < 2; nt++)
#pragma unroll
            for (int e = 0; e < 4; e++) acc[mt][nt][e] = 0.f;

    // precompute ldmatrix lane addresses
    uint32_t aaddr[2][2], baddr[2];      // A: [mt][h]; B: [h]
    {
        int arow = wm * 32 + (lane & 15);
        int acol = (lane >> 4) * 8;
        aaddr[0][0] = (uint32_t)__cvta_generic_to_shared(&As[0][arow][acol]);
        aaddr[1][0] = (uint32_t)__cvta_generic_to_shared(&As[0][arow + 16][acol]);
        aaddr[0][1] = (uint32_t)__cvta_generic_to_shared(&As[1][arow][acol]);
        aaddr[1][1] = (uint32_t)__cvta_generic_to_shared(&As[1][arow + 16][acol]);
        int brow = wn * 16 + (lane & 7) + ((lane >> 4) << 3);
        int bcol = ((lane >> 3) & 1) * 8;
        baddr[0] = (uint32_t)__cvta_generic_to_shared(&Bs[0][brow][bcol]);
        baddr[1] = (uint32_t)__cvta_generic_to_shared(&Bs[1][brow][bcol]);
    }

    // A loader: aq = 8-col group 0..3, ar = row 0..63; rows ar, ar+64
    const int aq = t & 3;
    const int ar = t >> 2;
    // B loader: bn = n row 0..31, bseg = 4-col group 0..7
    const int bn = t >> 3;
    const int bseg = t & 7;

    const __nv_bfloat16* __restrict__ Xh = g_eh[k];
    const __nv_bfloat16* __restrict__ Xl = g_el[k];
    const __nv_bfloat16* __restrict__ Mh = g_msgh[j];
    const __nv_bfloat16* __restrict__ Ml = g_msgl[j];

    // -------- software-pipelined K loop: register double-buffer --------
    uint4 sh0, sh1, sl0, sl1;
    uint2 swh, swl;
    {
        // prologue: load kt = 0
        int colbase = aq * 8;
        size_t o0 = (size_t)(m0 + ar) * DD + colbase;
        size_t o1 = (size_t)(m0 + ar + 64) * DD + colbase;
        sh0 = *(const uint4*)&Xh[o0];
        sh1 = *(const uint4*)&Xh[o1];
        sl0 = *(const uint4*)&Xl[o0];
        sl1 = *(const uint4*)&Xl[o1];
        size_t woff = (size_t)(n0 + bn) * 512 + bseg * 4;
        swh = *(const uint2*)&g_Wt_hi[woff];
        swl = *(const uint2*)&g_Wt_lo[woff];
    }

    for (int kt = 0; kt < 512; kt += 32) {
        // commit staged tile to smem
        *(uint4*)&As[0][ar][aq * 8]      = sh0;
        *(uint4*)&As[0][ar + 64][aq * 8] = sh1;
        *(uint4*)&As[1][ar][aq * 8]      = sl0;
        *(uint4*)&As[1][ar + 64][aq * 8] = sl1;
        *(uint2*)&Bs[0][bn][bseg * 4] = swh;
        *(uint2*)&Bs[1][bn][bseg * 4] = swl;
        __syncthreads();

        // issue loads for kt+32 (overlapped with compute below)
        int ktn = kt + 32;
        if (ktn < 512) {
            const __nv_bfloat16* Ah = (ktn < 256) ? Xh : Mh;
            const __nv_bfloat16* Al = (ktn < 256) ? Xl : Ml;
            int colbase = (ktn & 255) + aq * 8;
            size_t o0 = (size_t)(m0 + ar) * DD + colbase;
            size_t o1 = (size_t)(m0 + ar + 64) * DD + colbase;
            sh0 = *(const uint4*)&Ah[o0];
            sh1 = *(const uint4*)&Ah[o1];
            sl0 = *(const uint4*)&Al[o0];
            sl1 = *(const uint4*)&Al[o1];
            size_t woff = (size_t)(n0 + bn) * 512 + ktn + bseg * 4;
            swh = *(const uint2*)&g_Wt_hi[woff];
            swl = *(const uint2*)&g_Wt_lo[woff];
        }

#pragma unroll
        for (int sub = 0; sub < 2; sub++) {
            uint32_t off = sub * 32;     // 16 bf16 = 32 bytes
            uint32_t ah0[4], ah1[4], al0[4], al1[4];
            uint32_t bh[4], bl[4];
            ldsm4(ah0, aaddr[0][0] + off);
            ldsm4(ah1, aaddr[1][0] + off);
            ldsm4(al0, aaddr[0][1] + off);
            ldsm4(al1, aaddr[1][1] + off);
            ldsm4(bh, baddr[0] + off);
            ldsm4(bl, baddr[1] + off);
#pragma unroll
            for (int mt = 0; mt < 2; mt++) {
                const uint32_t* ah = mt ? ah1 : ah0;
                const uint32_t* al = mt ? al1 : al0;
                mma16816(acc[mt][0], ah, bh + 0);
                mma16816(acc[mt][0], ah, bl + 0);
                mma16816(acc[mt][0], al, bh + 0);
                mma16816(acc[mt][1], ah, bh + 2);
                mma16816(acc[mt][1], ah, bl + 2);
                mma16816(acc[mt][1], al, bh + 2);
            }
        }
        __syncthreads();
    }

    // epilogue: + bias, relu, store fp32 + bf16 hi/lo planes into e_{k+1}
    float* O = g_e[k + 1];
    __nv_bfloat16* Oh = g_eh[k + 1];
    __nv_bfloat16* Ol = g_el[k + 1];
#pragma unroll
    for (int mt = 0; mt < 2; mt++) {
        int row = m0 + wm * 32 + mt * 16 + g8;
#pragma unroll
        for (int nt = 0; nt < 2; nt++) {
            int col = n0 + wn * 16 + nt * 8 + tq * 2;
            float b0 = bias[col], b1 = bias[col + 1];
            float2 o0, o1;
            o0.x = fmaxf(acc[mt][nt][0] + b0, 0.f);
            o0.y = fmaxf(acc[mt][nt][1] + b1, 0.f);
            o1.x = fmaxf(acc[mt][nt][2] + b0, 0.f);
            o1.y = fmaxf(acc[mt][nt][3] + b1, 0.f);
            *(float2*)&O[(size_t)row * DD + col] = o0;
            *(float2*)&O[(size_t)(row + 8) * DD + col] = o1;
            __nv_bfloat162 h0 = __floats2bfloat162_rn(o0.x, o0.y);
            __nv_bfloat162 l0 = __floats2bfloat162_rn(o0.x - __bfloat162float(h0.x),
                                                      o0.y - __bfloat162float(h0.y));
            __nv_bfloat162 h1 = __floats2bfloat162_rn(o1.x, o1.y);
            __nv_bfloat162 l1 = __floats2bfloat162_rn(o1.x - __bfloat162float(h1.x),
                                                      o1.y - __bfloat162float(h1.y));
            *(__nv_bfloat162*)&Oh[(size_t)row * DD + col]       = h0;
            *(__nv_bfloat162*)&Ol[(size_t)row * DD + col]       = l0;
            *(__nv_bfloat162*)&Oh[(size_t)(row + 8) * DD + col] = h1;
            *(__nv_bfloat162*)&Ol[(size_t)(row + 8) * DD + col] = l1;
        }
    }
    // conflict gate arrival (job 0 only)
    if (conflict && j == 0) {
        __syncthreads();
        __threadfence();
        if (t == 0) atomicAdd(&g_done, 1u);
    }
}

// ---------------- final: out = pi[0] + pi[1] ----------------
__global__ void sum_out_k(float* __restrict__ out) {
    int t0 = blockIdx.x * blockDim.x + threadIdx.x;
    int stride = gridDim.x * blockDim.x;
    const float4* p0 = (const float4*)g_pi[0];
    const float4* p1 = (const float4*)g_pi[1];
    float4* o4 = (float4*)out;
    int total = NN * CC / 4;
    for (int idx = t0; idx < total; idx += stride) {
        float4 a = p0[idx], b = p1[idx];
        o4[idx] = make_float4(a.x + b.x, a.y + b.y, a.z + b.z, a.w + b.w);
    }
}

// ---------------- launch ----------------
extern "C" void kernel_launch(void* const* d_in, const int* in_sizes, int n_in,
                              void* d_out, int out_size) {
    const float* embeddings = (const float*)d_in[0];
    const float* Wself      = (const float*)d_in[1];
    const float* Wnbr       = (const float*)d_in[2];
    const float* bvec       = (const float*)d_in[3];
    const int*   variants   = (const int*)d_in[4];
    const int*   original   = (const int*)d_in[5];
    const int*   edge_index = (const int*)d_in[6];
    float* out = (float*)d_out;
    int E = in_sizes[6] / 2;

    s1_init_k<<<512, 256>>>(embeddings, Wself, Wnbr);
    s2_prep_count_k<<<129, 256>>>(variants, original, edge_index, E);
    s3_scan_fill_k<<<1, 1024>>>(edge_index, E);

    for (int i = 0; i < LL; i++) {
        q_msg_k<<<dim3(NN, 2), 64>>>(i);
        r_k<<<257, 256>>>(original, bvec, i);
    }

    sum_out_k<<<1024, 256>>>(out);
}